// round 1
// baseline (speedup 1.0000x reference)
#include <cuda_runtime.h>
#include <math_constants.h>

#define D_MODEL 1024
#define SEQ     2048
#define BATCH   4
#define NHEAD   16
#define HDIM    64
#define MTOT    (BATCH * SEQ)

// -------- scratch (allocation-free: __device__ globals) --------
__device__ float g_Q[(size_t)MTOT * D_MODEL];
__device__ float g_K[(size_t)MTOT * D_MODEL];
__device__ float g_V[(size_t)MTOT * D_MODEL];
__device__ float g_C[(size_t)MTOT * D_MODEL];

// ---------------- SGEMM: C = A[M,K] @ B[K,N] (+ optional bias) ----------------
#define BM 128
#define BN 128
#define BK 16

__global__ __launch_bounds__(256) void sgemm_kernel(
    const float* __restrict__ A, const float* __restrict__ B,
    const float* __restrict__ bias, float* __restrict__ C,
    int M, int N, int K)
{
    __shared__ float As[BK][BM];   // A tile stored transposed: As[k][m]
    __shared__ float Bs[BK][BN];

    const int tid = threadIdx.x;
    const int bm  = blockIdx.y * BM;
    const int bn  = blockIdx.x * BN;
    const int tx  = tid & 15, ty = tid >> 4;
    const int row0 = ty * 8, col0 = tx * 8;

    float acc[8][8] = {};

    for (int k0 = 0; k0 < K; k0 += BK) {
        #pragma unroll
        for (int u = 0; u < 2; u++) {
            int f = tid + u * 256;                 // 512 float4 loads each for A & B
            int m  = f >> 2, kq = (f & 3) << 2;    // A: 128 rows x 16 k (float4 along k)
            float4 a = *(const float4*)(A + (size_t)(bm + m) * K + k0 + kq);
            As[kq + 0][m] = a.x; As[kq + 1][m] = a.y;
            As[kq + 2][m] = a.z; As[kq + 3][m] = a.w;
            int kk = f >> 5, nq = (f & 31) << 2;   // B: 16 rows x 128 n (float4 along n)
            *(float4*)&Bs[kk][nq] =
                *(const float4*)(B + (size_t)(k0 + kk) * N + bn + nq);
        }
        __syncthreads();

        #pragma unroll
        for (int k = 0; k < BK; k++) {
            float a[8], b[8];
            *(float4*)(a)     = *(const float4*)&As[k][row0];
            *(float4*)(a + 4) = *(const float4*)&As[k][row0 + 4];
            *(float4*)(b)     = *(const float4*)&Bs[k][col0];
            *(float4*)(b + 4) = *(const float4*)&Bs[k][col0 + 4];
            #pragma unroll
            for (int i = 0; i < 8; i++)
                #pragma unroll
                for (int j = 0; j < 8; j++)
                    acc[i][j] += a[i] * b[j];
        }
        __syncthreads();
    }

    float bv[8];
    #pragma unroll
    for (int j = 0; j < 8; j++) bv[j] = bias ? bias[bn + col0 + j] : 0.0f;

    #pragma unroll
    for (int i = 0; i < 8; i++) {
        float* cp = C + (size_t)(bm + row0 + i) * N + bn + col0;
        float4 r0 = make_float4(acc[i][0] + bv[0], acc[i][1] + bv[1],
                                acc[i][2] + bv[2], acc[i][3] + bv[3]);
        float4 r1 = make_float4(acc[i][4] + bv[4], acc[i][5] + bv[5],
                                acc[i][6] + bv[6], acc[i][7] + bv[7]);
        *(float4*)cp       = r0;
        *(float4*)(cp + 4) = r1;
    }
}

// ---------------- Flash attention (fp32, causal) ----------------
// One block per (q-tile of 64 rows, head, batch). 256 threads; each thread
// owns a 4x4 patch of the 64x64 score tile and of the 64x64 output tile.
// Online softmax stats live in registers, reduced across the 16 threads of a
// row with warp shuffles (row's 16 threads share a half-warp).
__global__ __launch_bounds__(256) void attn_kernel(
    const float* __restrict__ Q, const float* __restrict__ K,
    const float* __restrict__ V, float* __restrict__ CTX)
{
    __shared__ float sQ[64 * 64];    // [r][d]
    __shared__ float sKV[64 * 64];   // K phase: [d][kcol]; V phase: [kpos][c]
    __shared__ float sS[64 * 64];    // P tile [r][k]
    // total = 48 KB static, exactly at the limit

    const int tid = threadIdx.x;
    const int qt = blockIdx.x, h = blockIdx.y, b = blockIdx.z;
    const int tx = tid & 15, ty = tid >> 4;
    const size_t base = ((size_t)b * SEQ) * D_MODEL + (size_t)h * HDIM;

    // Load Q tile [64 x 64], natural layout
    #pragma unroll
    for (int u = 0; u < 4; u++) {
        int f = tid + u * 256;
        int r = f >> 4, c = (f & 15) << 2;
        *(float4*)&sQ[r * 64 + c] =
            *(const float4*)(Q + base + (size_t)(qt * 64 + r) * D_MODEL + c);
    }

    float o[4][4] = {};
    float m[4], l[4];
    #pragma unroll
    for (int i = 0; i < 4; i++) { m[i] = -CUDART_INF_F; l[i] = 0.0f; }
    const float scale = 0.125f;  // 1/sqrt(64)

    __syncthreads();

    for (int jt = 0; jt <= qt; jt++) {
        // Load K tile, stored d-major: sKV[d][kcol]
        #pragma unroll
        for (int u = 0; u < 4; u++) {
            int f = tid + u * 256;
            int r = f >> 4, c = (f & 15) << 2;
            float4 kk = *(const float4*)(K + base + (size_t)(jt * 64 + r) * D_MODEL + c);
            sKV[(c + 0) * 64 + r] = kk.x;
            sKV[(c + 1) * 64 + r] = kk.y;
            sKV[(c + 2) * 64 + r] = kk.z;
            sKV[(c + 3) * 64 + r] = kk.w;
        }
        __syncthreads();

        // S = Q K^T (64x64), 4x4 per thread
        float s[4][4] = {};
        #pragma unroll
        for (int d = 0; d < 64; d += 4) {
            float qv[4][4], kv[4][4];
            #pragma unroll
            for (int i = 0; i < 4; i++)
                *(float4*)qv[i] = *(const float4*)&sQ[(ty * 4 + i) * 64 + d];
            #pragma unroll
            for (int t = 0; t < 4; t++)
                *(float4*)kv[t] = *(const float4*)&sKV[(d + t) * 64 + tx * 4];
            #pragma unroll
            for (int i = 0; i < 4; i++)
                #pragma unroll
                for (int j = 0; j < 4; j++)
                    s[i][j] += qv[i][0] * kv[0][j] + qv[i][1] * kv[1][j]
                             + qv[i][2] * kv[2][j] + qv[i][3] * kv[3][j];
        }
        __syncthreads();   // everyone done reading sKV (K phase)

        // Load V tile, natural layout: sKV[kpos][c]
        #pragma unroll
        for (int u = 0; u < 4; u++) {
            int f = tid + u * 256;
            int r = f >> 4, c = (f & 15) << 2;
            *(float4*)&sKV[r * 64 + c] =
                *(const float4*)(V + base + (size_t)(jt * 64 + r) * D_MODEL + c);
        }

        // Online softmax update (registers + shuffles)
        const bool diag = (jt == qt);
        #pragma unroll
        for (int i = 0; i < 4; i++) {
            int rq = ty * 4 + i;
            float mt = -CUDART_INF_F;
            #pragma unroll
            for (int j = 0; j < 4; j++) {
                float v = s[i][j] * scale;
                if (diag && (tx * 4 + j) > rq) v = -CUDART_INF_F;
                s[i][j] = v;
                mt = fmaxf(mt, v);
            }
            #pragma unroll
            for (int w = 1; w < 16; w <<= 1)
                mt = fmaxf(mt, __shfl_xor_sync(0xffffffffu, mt, w));
            float mn    = fmaxf(m[i], mt);
            float alpha = __expf(m[i] - mn);
            float p[4];
            float ls = 0.0f;
            #pragma unroll
            for (int j = 0; j < 4; j++) {
                p[j] = __expf(s[i][j] - mn);
                ls += p[j];
            }
            #pragma unroll
            for (int w = 1; w < 16; w <<= 1)
                ls += __shfl_xor_sync(0xffffffffu, ls, w);
            l[i] = l[i] * alpha + ls;
            m[i] = mn;
            #pragma unroll
            for (int j = 0; j < 4; j++) o[i][j] *= alpha;
            *(float4*)&sS[rq * 64 + tx * 4] = *(float4*)p;
        }
        __syncthreads();   // V tile + P tile visible

        // O += P V
        #pragma unroll
        for (int k = 0; k < 64; k += 4) {
            float pv[4][4], vv[4][4];
            #pragma unroll
            for (int i = 0; i < 4; i++)
                *(float4*)pv[i] = *(const float4*)&sS[(ty * 4 + i) * 64 + k];
            #pragma unroll
            for (int t = 0; t < 4; t++)
                *(float4*)vv[t] = *(const float4*)&sKV[(k + t) * 64 + tx * 4];
            #pragma unroll
            for (int i = 0; i < 4; i++)
                #pragma unroll
                for (int j = 0; j < 4; j++)
                    o[i][j] += pv[i][0] * vv[0][j] + pv[i][1] * vv[1][j]
                             + pv[i][2] * vv[2][j] + pv[i][3] * vv[3][j];
        }
        __syncthreads();   // done with sKV / sS before next iteration
    }

    // Finalize and write ctx tile
    #pragma unroll
    for (int i = 0; i < 4; i++) {
        float inv = 1.0f / l[i];
        float4 r = make_float4(o[i][0] * inv, o[i][1] * inv,
                               o[i][2] * inv, o[i][3] * inv);
        *(float4*)(CTX + base + (size_t)(qt * 64 + ty * 4 + i) * D_MODEL + tx * 4) = r;
    }
}

// ---------------- launcher ----------------
extern "C" void kernel_launch(void* const* d_in, const int* in_sizes, int n_in,
                              void* d_out, int out_size)
{
    const float* x  = (const float*)d_in[0];
    const float* Wq = (const float*)d_in[1];
    const float* Wk = (const float*)d_in[2];
    const float* Wv = (const float*)d_in[3];
    const float* Wo = (const float*)d_in[4];
    const float* bo = (const float*)d_in[5];
    float* out = (float*)d_out;

    float *Qp, *Kp, *Vp, *Cp;
    cudaGetSymbolAddress((void**)&Qp, g_Q);
    cudaGetSymbolAddress((void**)&Kp, g_K);
    cudaGetSymbolAddress((void**)&Vp, g_V);
    cudaGetSymbolAddress((void**)&Cp, g_C);

    dim3 gridG(D_MODEL / BN, MTOT / BM);   // (8, 64)
    sgemm_kernel<<<gridG, 256>>>(x, Wq, nullptr, Qp, MTOT, D_MODEL, D_MODEL);
    sgemm_kernel<<<gridG, 256>>>(x, Wk, nullptr, Kp, MTOT, D_MODEL, D_MODEL);
    sgemm_kernel<<<gridG, 256>>>(x, Wv, nullptr, Vp, MTOT, D_MODEL, D_MODEL);

    dim3 gridA(SEQ / 64, NHEAD, BATCH);    // (32, 16, 4)
    attn_kernel<<<gridA, 256>>>(Qp, Kp, Vp, Cp);

    sgemm_kernel<<<gridG, 256>>>(Cp, Wo, bo, out, MTOT, D_MODEL, D_MODEL);
}

// round 2
// speedup vs baseline: 1.3595x; 1.3595x over previous
#include <cuda_runtime.h>
#include <cuda_bf16.h>
#include <math_constants.h>
#include <cstdint>

#define D_MODEL 1024
#define SEQ     2048
#define BATCH   4
#define NHEAD   16
#define HDIM    64
#define MTOT    (BATCH * SEQ)
#define KP      (3 * D_MODEL)      // tripled-K for bf16x3 compensation

// -------- scratch (allocation-free: __device__ globals) --------
__device__ float g_Q[(size_t)MTOT * D_MODEL];
__device__ float g_K[(size_t)MTOT * D_MODEL];
__device__ float g_V[(size_t)MTOT * D_MODEL];
__device__ float g_C[(size_t)MTOT * D_MODEL];
__device__ __nv_bfloat16 g_xc[(size_t)MTOT * KP];      // [Ahi | Alo | Ahi]
__device__ __nv_bfloat16 g_cc[(size_t)MTOT * KP];
__device__ __nv_bfloat16 g_wq[(size_t)D_MODEL * KP];   // transposed: [n][Bhi;Bhi;Blo]
__device__ __nv_bfloat16 g_wk[(size_t)D_MODEL * KP];
__device__ __nv_bfloat16 g_wv[(size_t)D_MODEL * KP];
__device__ __nv_bfloat16 g_wo[(size_t)D_MODEL * KP];

// ---------------- conversion kernels ----------------
// Activation: X [M][1024] fp32 -> O [M][3072] bf16 as [hi | lo | hi]
__global__ void convert_a_kernel(const float* __restrict__ X,
                                 __nv_bfloat16* __restrict__ O, int M)
{
    size_t i = (size_t)blockIdx.x * blockDim.x + threadIdx.x;
    if (i >= (size_t)M * D_MODEL) return;
    int m = (int)(i >> 10), k = (int)(i & 1023);
    float x = X[i];
    __nv_bfloat16 hi = __float2bfloat16(x);
    __nv_bfloat16 lo = __float2bfloat16(x - __bfloat162float(hi));
    __nv_bfloat16* row = O + (size_t)m * KP;
    row[k] = hi; row[k + D_MODEL] = lo; row[k + 2 * D_MODEL] = hi;
}

// Weight: W [1024 k][1024 n] fp32 -> O [n][3072] bf16 as [hi ; hi ; lo] along k'
__global__ void convert_w_kernel(const float* __restrict__ W,
                                 __nv_bfloat16* __restrict__ O)
{
    int i = blockIdx.x * blockDim.x + threadIdx.x;   // n fastest -> coalesced read
    int k = i >> 10, n = i & 1023;
    float w = W[(size_t)k * D_MODEL + n];
    __nv_bfloat16 hi = __float2bfloat16(w);
    __nv_bfloat16 lo = __float2bfloat16(w - __bfloat162float(hi));
    __nv_bfloat16* row = O + (size_t)n * KP;
    row[k] = hi; row[k + D_MODEL] = hi; row[k + 2 * D_MODEL] = lo;
}

// ---------------- bf16 tensor-core GEMM: C[M,N] = A'[M,KP] @ B't[N,KP]^T ----------------
#define GBM 128
#define GBN 128
#define GBK 64
#define SSTR 72                      // padded smem row stride (bf16 elems)
#define GEMM_SMEM (2 * (GBM + GBN) * SSTR * 2)   // 73728 bytes (2 stages)

__device__ __forceinline__ void cp_async16(uint32_t smem, const void* gptr) {
    asm volatile("cp.async.cg.shared.global [%0], [%1], 16;\n"
                 :: "r"(smem), "l"(gptr) : "memory");
}

#define MMA16816(d, a, b)                                                     \
    asm volatile(                                                             \
        "mma.sync.aligned.m16n8k16.row.col.f32.bf16.bf16.f32 "                \
        "{%0,%1,%2,%3}, {%4,%5,%6,%7}, {%8,%9}, {%0,%1,%2,%3};"               \
        : "+f"(d[0]), "+f"(d[1]), "+f"(d[2]), "+f"(d[3])                      \
        : "r"(a[0]), "r"(a[1]), "r"(a[2]), "r"(a[3]), "r"(b[0]), "r"(b[1]))

__global__ __launch_bounds__(256) void hgemm3_kernel(
    const __nv_bfloat16* __restrict__ A,   // [M][KP] row-major
    const __nv_bfloat16* __restrict__ Bt,  // [N][KP] row-major (pre-transposed)
    const float* __restrict__ bias,
    float* __restrict__ C, int M, int N)
{
    extern __shared__ __nv_bfloat16 sm[];
    __nv_bfloat16* sA = sm;                          // 2 stages * 128*72
    __nv_bfloat16* sB = sm + 2 * GBM * SSTR;

    const int tid  = threadIdx.x;
    const int bm   = blockIdx.y * GBM;
    const int bn   = blockIdx.x * GBN;
    const int warp = tid >> 5, lane = tid & 31;
    const int wm = warp >> 1, wn = warp & 1;         // 4 x 2 warp grid
    const int m_base = wm * 32, n_base = wn * 64;    // warp tile 32m x 64n
    const int g = lane >> 2, t = lane & 3;

    const uint32_t sA0 = (uint32_t)__cvta_generic_to_shared(sA);
    const uint32_t sB0 = (uint32_t)__cvta_generic_to_shared(sB);

    float acc[2][8][4] = {};

    auto issue_tile = [&](int it, int stg) {
        int k0 = it * GBK;
        #pragma unroll
        for (int i = 0; i < 4; i++) {
            int idx = tid + i * 256;
            int row = idx >> 3, c = (idx & 7) * 8;          // 8 bf16 = 16B chunks
            cp_async16(sA0 + (uint32_t)(((stg * GBM + row) * SSTR + c) * 2),
                       A + (size_t)(bm + row) * KP + k0 + c);
            cp_async16(sB0 + (uint32_t)(((stg * GBN + row) * SSTR + c) * 2),
                       Bt + (size_t)(bn + row) * KP + k0 + c);
        }
        asm volatile("cp.async.commit_group;\n" ::: "memory");
    };

    issue_tile(0, 0);
    const int nIter = KP / GBK;                      // 48

    for (int it = 0; it < nIter; ++it) {
        asm volatile("cp.async.wait_group 0;\n" ::: "memory");
        __syncthreads();
        if (it + 1 < nIter) issue_tile(it + 1, (it + 1) & 1);

        const __nv_bfloat16* As = sA + (it & 1) * GBM * SSTR;
        const __nv_bfloat16* Bs = sB + (it & 1) * GBN * SSTR;

        #pragma unroll
        for (int ks = 0; ks < GBK / 16; ks++) {
            const int kk = ks * 16;
            uint32_t aF[2][4], bF[8][2];
            #pragma unroll
            for (int mt = 0; mt < 2; mt++) {
                const __nv_bfloat16* p = As + (m_base + mt * 16 + g) * SSTR + kk + 2 * t;
                aF[mt][0] = *(const uint32_t*)(p);
                aF[mt][1] = *(const uint32_t*)(p + 8 * SSTR);
                aF[mt][2] = *(const uint32_t*)(p + 8);
                aF[mt][3] = *(const uint32_t*)(p + 8 * SSTR + 8);
            }
            #pragma unroll
            for (int nt = 0; nt < 8; nt++) {
                const __nv_bfloat16* p = Bs + (n_base + nt * 8 + g) * SSTR + kk + 2 * t;
                bF[nt][0] = *(const uint32_t*)(p);
                bF[nt][1] = *(const uint32_t*)(p + 8);
            }
            #pragma unroll
            for (int mt = 0; mt < 2; mt++)
                #pragma unroll
                for (int nt = 0; nt < 8; nt++)
                    MMA16816(acc[mt][nt], aF[mt], bF[nt]);
        }
        __syncthreads();
    }

    #pragma unroll
    for (int mt = 0; mt < 2; mt++) {
        int r0 = bm + m_base + mt * 16 + g;
        #pragma unroll
        for (int nt = 0; nt < 8; nt++) {
            int col = bn + n_base + nt * 8 + 2 * t;
            float b0 = 0.f, b1 = 0.f;
            if (bias) { b0 = bias[col]; b1 = bias[col + 1]; }
            float2 v0 = make_float2(acc[mt][nt][0] + b0, acc[mt][nt][1] + b1);
            float2 v1 = make_float2(acc[mt][nt][2] + b0, acc[mt][nt][3] + b1);
            *(float2*)&C[(size_t)r0 * N + col]       = v0;
            *(float2*)&C[(size_t)(r0 + 8) * N + col] = v1;
        }
    }
}

// ---------------- Flash attention (fp32, causal) — unchanged from R1 ----------------
__global__ __launch_bounds__(256) void attn_kernel(
    const float* __restrict__ Q, const float* __restrict__ K,
    const float* __restrict__ V, float* __restrict__ CTX)
{
    __shared__ float sQ[64 * 64];
    __shared__ float sKV[64 * 64];
    __shared__ float sS[64 * 64];

    const int tid = threadIdx.x;
    const int qt = blockIdx.x, h = blockIdx.y, b = blockIdx.z;
    const int tx = tid & 15, ty = tid >> 4;
    const size_t base = ((size_t)b * SEQ) * D_MODEL + (size_t)h * HDIM;

    #pragma unroll
    for (int u = 0; u < 4; u++) {
        int f = tid + u * 256;
        int r = f >> 4, c = (f & 15) << 2;
        *(float4*)&sQ[r * 64 + c] =
            *(const float4*)(Q + base + (size_t)(qt * 64 + r) * D_MODEL + c);
    }

    float o[4][4] = {};
    float m[4], l[4];
    #pragma unroll
    for (int i = 0; i < 4; i++) { m[i] = -CUDART_INF_F; l[i] = 0.0f; }
    const float scale = 0.125f;

    __syncthreads();

    for (int jt = 0; jt <= qt; jt++) {
        #pragma unroll
        for (int u = 0; u < 4; u++) {
            int f = tid + u * 256;
            int r = f >> 4, c = (f & 15) << 2;
            float4 kk = *(const float4*)(K + base + (size_t)(jt * 64 + r) * D_MODEL + c);
            sKV[(c + 0) * 64 + r] = kk.x;
            sKV[(c + 1) * 64 + r] = kk.y;
            sKV[(c + 2) * 64 + r] = kk.z;
            sKV[(c + 3) * 64 + r] = kk.w;
        }
        __syncthreads();

        float s[4][4] = {};
        #pragma unroll
        for (int d = 0; d < 64; d += 4) {
            float qv[4][4], kv[4][4];
            #pragma unroll
            for (int i = 0; i < 4; i++)
                *(float4*)qv[i] = *(const float4*)&sQ[(ty * 4 + i) * 64 + d];
            #pragma unroll
            for (int tt = 0; tt < 4; tt++)
                *(float4*)kv[tt] = *(const float4*)&sKV[(d + tt) * 64 + tx * 4];
            #pragma unroll
            for (int i = 0; i < 4; i++)
                #pragma unroll
                for (int j = 0; j < 4; j++)
                    s[i][j] += qv[i][0] * kv[0][j] + qv[i][1] * kv[1][j]
                             + qv[i][2] * kv[2][j] + qv[i][3] * kv[3][j];
        }
        __syncthreads();

        #pragma unroll
        for (int u = 0; u < 4; u++) {
            int f = tid + u * 256;
            int r = f >> 4, c = (f & 15) << 2;
            *(float4*)&sKV[r * 64 + c] =
                *(const float4*)(V + base + (size_t)(jt * 64 + r) * D_MODEL + c);
        }

        const bool diag = (jt == qt);
        #pragma unroll
        for (int i = 0; i < 4; i++) {
            int rq = ty * 4 + i;
            float mt = -CUDART_INF_F;
            #pragma unroll
            for (int j = 0; j < 4; j++) {
                float v = s[i][j] * scale;
                if (diag && (tx * 4 + j) > rq) v = -CUDART_INF_F;
                s[i][j] = v;
                mt = fmaxf(mt, v);
            }
            #pragma unroll
            for (int w = 1; w < 16; w <<= 1)
                mt = fmaxf(mt, __shfl_xor_sync(0xffffffffu, mt, w));
            float mn    = fmaxf(m[i], mt);
            float alpha = __expf(m[i] - mn);
            float p[4];
            float ls = 0.0f;
            #pragma unroll
            for (int j = 0; j < 4; j++) {
                p[j] = __expf(s[i][j] - mn);
                ls += p[j];
            }
            #pragma unroll
            for (int w = 1; w < 16; w <<= 1)
                ls += __shfl_xor_sync(0xffffffffu, ls, w);
            l[i] = l[i] * alpha + ls;
            m[i] = mn;
            #pragma unroll
            for (int j = 0; j < 4; j++) o[i][j] *= alpha;
            *(float4*)&sS[rq * 64 + tx * 4] = *(float4*)p;
        }
        __syncthreads();

        #pragma unroll
        for (int k = 0; k < 64; k += 4) {
            float pv[4][4], vv[4][4];
            #pragma unroll
            for (int i = 0; i < 4; i++)
                *(float4*)pv[i] = *(const float4*)&sS[(ty * 4 + i) * 64 + k];
            #pragma unroll
            for (int tt = 0; tt < 4; tt++)
                *(float4*)vv[tt] = *(const float4*)&sKV[(k + tt) * 64 + tx * 4];
            #pragma unroll
            for (int i = 0; i < 4; i++)
                #pragma unroll
                for (int j = 0; j < 4; j++)
                    o[i][j] += pv[i][0] * vv[0][j] + pv[i][1] * vv[1][j]
                             + pv[i][2] * vv[2][j] + pv[i][3] * vv[3][j];
        }
        __syncthreads();
    }

    #pragma unroll
    for (int i = 0; i < 4; i++) {
        float inv = 1.0f / l[i];
        float4 r = make_float4(o[i][0] * inv, o[i][1] * inv,
                               o[i][2] * inv, o[i][3] * inv);
        *(float4*)(CTX + base + (size_t)(qt * 64 + ty * 4 + i) * D_MODEL + tx * 4) = r;
    }
}

// ---------------- launcher ----------------
extern "C" void kernel_launch(void* const* d_in, const int* in_sizes, int n_in,
                              void* d_out, int out_size)
{
    const float* x  = (const float*)d_in[0];
    const float* Wq = (const float*)d_in[1];
    const float* Wk = (const float*)d_in[2];
    const float* Wv = (const float*)d_in[3];
    const float* Wo = (const float*)d_in[4];
    const float* bo = (const float*)d_in[5];
    float* out = (float*)d_out;

    float *Qp, *Kp, *Vp, *Cp;
    __nv_bfloat16 *xc, *cc, *wq, *wk, *wv, *wo;
    cudaGetSymbolAddress((void**)&Qp, g_Q);
    cudaGetSymbolAddress((void**)&Kp, g_K);
    cudaGetSymbolAddress((void**)&Vp, g_V);
    cudaGetSymbolAddress((void**)&Cp, g_C);
    cudaGetSymbolAddress((void**)&xc, g_xc);
    cudaGetSymbolAddress((void**)&cc, g_cc);
    cudaGetSymbolAddress((void**)&wq, g_wq);
    cudaGetSymbolAddress((void**)&wk, g_wk);
    cudaGetSymbolAddress((void**)&wv, g_wv);
    cudaGetSymbolAddress((void**)&wo, g_wo);

    static bool attr_done = false;
    if (!attr_done) {
        cudaFuncSetAttribute(hgemm3_kernel,
                             cudaFuncAttributeMaxDynamicSharedMemorySize, GEMM_SMEM);
        attr_done = true;
    }

    // conversions
    convert_a_kernel<<<(MTOT * D_MODEL) / 256, 256>>>(x, xc, MTOT);
    convert_w_kernel<<<(D_MODEL * D_MODEL) / 256, 256>>>(Wq, wq);
    convert_w_kernel<<<(D_MODEL * D_MODEL) / 256, 256>>>(Wk, wk);
    convert_w_kernel<<<(D_MODEL * D_MODEL) / 256, 256>>>(Wv, wv);
    convert_w_kernel<<<(D_MODEL * D_MODEL) / 256, 256>>>(Wo, wo);

    dim3 gridG(D_MODEL / GBN, MTOT / GBM);   // (8, 64)
    hgemm3_kernel<<<gridG, 256, GEMM_SMEM>>>(xc, wq, nullptr, Qp, MTOT, D_MODEL);
    hgemm3_kernel<<<gridG, 256, GEMM_SMEM>>>(xc, wk, nullptr, Kp, MTOT, D_MODEL);
    hgemm3_kernel<<<gridG, 256, GEMM_SMEM>>>(xc, wv, nullptr, Vp, MTOT, D_MODEL);

    dim3 gridA(SEQ / 64, NHEAD, BATCH);      // (32, 16, 4)
    attn_kernel<<<gridA, 256>>>(Qp, Kp, Vp, Cp);

    convert_a_kernel<<<(MTOT * D_MODEL) / 256, 256>>>(Cp, cc, MTOT);
    hgemm3_kernel<<<gridG, 256, GEMM_SMEM>>>(cc, wo, bo, out, MTOT, D_MODEL);
}

// round 3
// speedup vs baseline: 2.6118x; 1.9212x over previous
#include <cuda_runtime.h>
#include <cuda_bf16.h>
#include <math_constants.h>
#include <cstdint>

#define D_MODEL 1024
#define SEQ     2048
#define BATCH   4
#define NHEAD   16
#define HDIM    64
#define MTOT    (BATCH * SEQ)
#define KP      (3 * D_MODEL)      // tripled-K for bf16x3 compensation

// -------- scratch (allocation-free: __device__ globals) --------
__device__ float g_Q[(size_t)MTOT * D_MODEL];
__device__ float g_K[(size_t)MTOT * D_MODEL];
__device__ float g_V[(size_t)MTOT * D_MODEL];
__device__ float g_C[(size_t)MTOT * D_MODEL];
__device__ __nv_bfloat16 g_xc[(size_t)MTOT * KP];      // [Ahi | Alo | Ahi]
__device__ __nv_bfloat16 g_cc[(size_t)MTOT * KP];
__device__ __nv_bfloat16 g_wq[(size_t)D_MODEL * KP];   // transposed: [n][Bhi;Bhi;Blo]
__device__ __nv_bfloat16 g_wk[(size_t)D_MODEL * KP];
__device__ __nv_bfloat16 g_wv[(size_t)D_MODEL * KP];
__device__ __nv_bfloat16 g_wo[(size_t)D_MODEL * KP];

// ---------------- small helpers ----------------
__device__ __forceinline__ float bfr(float x) {      // round-trip through bf16
    return __bfloat162float(__float2bfloat16(x));
}
__device__ __forceinline__ uint32_t packbf(float lo, float hi) {
    uint32_t d;
    asm("cvt.rn.bf16x2.f32 %0, %1, %2;" : "=r"(d) : "f"(hi), "f"(lo));
    return d;
}
__device__ __forceinline__ float ex2f(float x) {
    float y; asm("ex2.approx.ftz.f32 %0, %1;" : "=f"(y) : "f"(x)); return y;
}
__device__ __forceinline__ void ldsm_x4(uint32_t* r, uint32_t a) {
    asm volatile("ldmatrix.sync.aligned.m8n8.x4.shared.b16 {%0,%1,%2,%3}, [%4];"
        : "=r"(r[0]), "=r"(r[1]), "=r"(r[2]), "=r"(r[3]) : "r"(a));
}
__device__ __forceinline__ void ldsm_x4_t(uint32_t* r, uint32_t a) {
    asm volatile("ldmatrix.sync.aligned.m8n8.x4.trans.shared.b16 {%0,%1,%2,%3}, [%4];"
        : "=r"(r[0]), "=r"(r[1]), "=r"(r[2]), "=r"(r[3]) : "r"(a));
}

#define MMA4(d, a, b0, b1)                                                    \
    asm volatile(                                                             \
        "mma.sync.aligned.m16n8k16.row.col.f32.bf16.bf16.f32 "                \
        "{%0,%1,%2,%3}, {%4,%5,%6,%7}, {%8,%9}, {%0,%1,%2,%3};"               \
        : "+f"(d[0]), "+f"(d[1]), "+f"(d[2]), "+f"(d[3])                      \
        : "r"(a[0]), "r"(a[1]), "r"(a[2]), "r"(a[3]), "r"(b0), "r"(b1))

// ---------------- conversion kernels ----------------
__global__ void convert_a_kernel(const float* __restrict__ X,
                                 __nv_bfloat16* __restrict__ O, int M)
{
    size_t i = (size_t)blockIdx.x * blockDim.x + threadIdx.x;
    if (i >= (size_t)M * D_MODEL) return;
    int m = (int)(i >> 10), k = (int)(i & 1023);
    float x = X[i];
    __nv_bfloat16 hi = __float2bfloat16(x);
    __nv_bfloat16 lo = __float2bfloat16(x - __bfloat162float(hi));
    __nv_bfloat16* row = O + (size_t)m * KP;
    row[k] = hi; row[k + D_MODEL] = lo; row[k + 2 * D_MODEL] = hi;
}

// Weight transpose via smem tile: coalesced reads AND writes.
__global__ void convert_w_kernel(const float* __restrict__ W,
                                 __nv_bfloat16* __restrict__ O)
{
    __shared__ float tile[32][33];
    const int n0 = blockIdx.x * 32, k0 = blockIdx.y * 32;
    const int tx = threadIdx.x, ty = threadIdx.y;      // (32, 8)
    #pragma unroll
    for (int i = 0; i < 4; i++)
        tile[ty + 8 * i][tx] = W[(size_t)(k0 + ty + 8 * i) * D_MODEL + n0 + tx];
    __syncthreads();
    #pragma unroll
    for (int i = 0; i < 4; i++) {
        int r = ty + 8 * i;                            // local n
        float w = tile[tx][r];                         // = W[k0+tx][n0+r]
        __nv_bfloat16 hi = __float2bfloat16(w);
        __nv_bfloat16 lo = __float2bfloat16(w - __bfloat162float(hi));
        __nv_bfloat16* row = O + (size_t)(n0 + r) * KP;
        row[k0 + tx] = hi;
        row[D_MODEL + k0 + tx] = hi;
        row[2 * D_MODEL + k0 + tx] = lo;
    }
}

// ---------------- bf16 tensor-core GEMM (unchanged from R2) ----------------
#define GBM 128
#define GBN 128
#define GBK 64
#define SSTR 72
#define GEMM_SMEM (2 * (GBM + GBN) * SSTR * 2)

__device__ __forceinline__ void cp_async16(uint32_t smem, const void* gptr) {
    asm volatile("cp.async.cg.shared.global [%0], [%1], 16;\n"
                 :: "r"(smem), "l"(gptr) : "memory");
}

__global__ __launch_bounds__(256) void hgemm3_kernel(
    const __nv_bfloat16* __restrict__ A,
    const __nv_bfloat16* __restrict__ Bt,
    const float* __restrict__ bias,
    float* __restrict__ C, int M, int N)
{
    extern __shared__ __nv_bfloat16 sm[];
    __nv_bfloat16* sA = sm;
    __nv_bfloat16* sB = sm + 2 * GBM * SSTR;

    const int tid  = threadIdx.x;
    const int bm   = blockIdx.y * GBM;
    const int bn   = blockIdx.x * GBN;
    const int warp = tid >> 5, lane = tid & 31;
    const int wm = warp >> 1, wn = warp & 1;
    const int m_base = wm * 32, n_base = wn * 64;
    const int g = lane >> 2, t = lane & 3;

    const uint32_t sA0 = (uint32_t)__cvta_generic_to_shared(sA);
    const uint32_t sB0 = (uint32_t)__cvta_generic_to_shared(sB);

    float acc[2][8][4] = {};

    auto issue_tile = [&](int it, int stg) {
        int k0 = it * GBK;
        #pragma unroll
        for (int i = 0; i < 4; i++) {
            int idx = tid + i * 256;
            int row = idx >> 3, c = (idx & 7) * 8;
            cp_async16(sA0 + (uint32_t)(((stg * GBM + row) * SSTR + c) * 2),
                       A + (size_t)(bm + row) * KP + k0 + c);
            cp_async16(sB0 + (uint32_t)(((stg * GBN + row) * SSTR + c) * 2),
                       Bt + (size_t)(bn + row) * KP + k0 + c);
        }
        asm volatile("cp.async.commit_group;\n" ::: "memory");
    };

    issue_tile(0, 0);
    const int nIter = KP / GBK;

    for (int it = 0; it < nIter; ++it) {
        asm volatile("cp.async.wait_group 0;\n" ::: "memory");
        __syncthreads();
        if (it + 1 < nIter) issue_tile(it + 1, (it + 1) & 1);

        const __nv_bfloat16* As = sA + (it & 1) * GBM * SSTR;
        const __nv_bfloat16* Bs = sB + (it & 1) * GBN * SSTR;

        #pragma unroll
        for (int ks = 0; ks < GBK / 16; ks++) {
            const int kk = ks * 16;
            uint32_t aF[2][4], bF[8][2];
            #pragma unroll
            for (int mt = 0; mt < 2; mt++) {
                const __nv_bfloat16* p = As + (m_base + mt * 16 + g) * SSTR + kk + 2 * t;
                aF[mt][0] = *(const uint32_t*)(p);
                aF[mt][1] = *(const uint32_t*)(p + 8 * SSTR);
                aF[mt][2] = *(const uint32_t*)(p + 8);
                aF[mt][3] = *(const uint32_t*)(p + 8 * SSTR + 8);
            }
            #pragma unroll
            for (int nt = 0; nt < 8; nt++) {
                const __nv_bfloat16* p = Bs + (n_base + nt * 8 + g) * SSTR + kk + 2 * t;
                bF[nt][0] = *(const uint32_t*)(p);
                bF[nt][1] = *(const uint32_t*)(p + 8);
            }
            #pragma unroll
            for (int mt = 0; mt < 2; mt++)
                #pragma unroll
                for (int nt = 0; nt < 8; nt++)
                    MMA4(acc[mt][nt], aF[mt], bF[nt][0], bF[nt][1]);
        }
        __syncthreads();
    }

    #pragma unroll
    for (int mt = 0; mt < 2; mt++) {
        int r0 = bm + m_base + mt * 16 + g;
        #pragma unroll
        for (int nt = 0; nt < 8; nt++) {
            int col = bn + n_base + nt * 8 + 2 * t;
            float b0 = 0.f, b1 = 0.f;
            if (bias) { b0 = bias[col]; b1 = bias[col + 1]; }
            float2 v0 = make_float2(acc[mt][nt][0] + b0, acc[mt][nt][1] + b1);
            float2 v1 = make_float2(acc[mt][nt][2] + b0, acc[mt][nt][3] + b1);
            *(float2*)&C[(size_t)r0 * N + col]       = v0;
            *(float2*)&C[(size_t)(r0 + 8) * N + col] = v1;
        }
    }
}

// ---------------- tensor-core flash attention (bf16x3 compensated) ----------------
// Block: 64 q-rows x one head. 4 warps, 16 m-rows each, full N per warp.
// smem: sQ[64][136] (Qhi cols 0-63 | Qlo 64-127), sK[64][136] (Khi|Klo),
//       sV[128][72] (rows 0-63 Vhi[kpos][c], rows 64-127 Vlo).
#define QSTR 136
#define VSTR 72
#define ATT_SMEM ((2 * 64 * QSTR + 128 * VSTR) * 2)   // 53248 bytes

__global__ __launch_bounds__(128) void attn_tc_kernel(
    const float* __restrict__ Q, const float* __restrict__ K,
    const float* __restrict__ V, float* __restrict__ CTX)
{
    extern __shared__ __nv_bfloat16 sm_at[];
    __nv_bfloat16* sQ = sm_at;
    __nv_bfloat16* sK = sQ + 64 * QSTR;
    __nv_bfloat16* sV = sK + 64 * QSTR;

    const int tid  = threadIdx.x;
    const int warp = tid >> 5, lane = tid & 31;
    const int g = lane >> 2, t = lane & 3;
    const int qt = blockIdx.x, h = blockIdx.y, b = blockIdx.z;
    const size_t base = ((size_t)b * SEQ) * D_MODEL + (size_t)h * HDIM;

    const uint32_t sQa = (uint32_t)__cvta_generic_to_shared(sQ);
    const uint32_t sKa = (uint32_t)__cvta_generic_to_shared(sK);
    const uint32_t sVa = (uint32_t)__cvta_generic_to_shared(sV);

    // ---- load Q tile fp32, split hi/lo into smem ----
    #pragma unroll
    for (int u = 0; u < 8; u++) {
        int idx = tid + u * 128;
        int r = idx >> 4, c = (idx & 15) << 2;
        float4 f = *(const float4*)(Q + base + (size_t)(qt * 64 + r) * D_MODEL + c);
        uint32_t h01 = packbf(f.x, f.y), h23 = packbf(f.z, f.w);
        uint32_t l01 = packbf(f.x - bfr(f.x), f.y - bfr(f.y));
        uint32_t l23 = packbf(f.z - bfr(f.z), f.w - bfr(f.w));
        *(uint2*)&sQ[r * QSTR + c]      = make_uint2(h01, h23);
        *(uint2*)&sQ[r * QSTR + 64 + c] = make_uint2(l01, l23);
    }
    __syncthreads();

    // ---- Q fragments into registers (kg 0-3: Qhi, kg 4-7: Qlo) ----
    uint32_t qF[8][4];
    {
        int rr = warp * 16 + (lane & 15);
        int cc = (lane >> 4) << 3;
        #pragma unroll
        for (int kg = 0; kg < 8; kg++)
            ldsm_x4(qF[kg], sQa + (uint32_t)((rr * QSTR + kg * 16 + cc) * 2));
    }

    float oAcc[8][4] = {};
    float mS[2] = {-CUDART_INF_F, -CUDART_INF_F};
    float lS[2] = {0.0f, 0.0f};

    const int krow = (lane & 7) | ((lane >> 4) << 3);   // K ldmatrix row offset
    const int kc8  = ((lane >> 3) & 1) << 3;            // K ldmatrix col offset
    const int vrow = lane & 15;                         // V ldmatrix row offset
    const int vc8  = (lane >> 4) << 3;                  // V ldmatrix col offset
    const float sc = 0.18033688011112042f;              // 0.125 * log2(e)

    for (int jt = 0; jt <= qt; jt++) {
        __syncthreads();   // previous iteration's smem reads complete
        // ---- load K,V tiles fp32, split hi/lo into smem ----
        #pragma unroll
        for (int u = 0; u < 8; u++) {
            int idx = tid + u * 128;
            int r = idx >> 4, c = (idx & 15) << 2;
            size_t goff = base + (size_t)(jt * 64 + r) * D_MODEL + c;
            float4 fk = *(const float4*)(K + goff);
            uint32_t h01 = packbf(fk.x, fk.y), h23 = packbf(fk.z, fk.w);
            uint32_t l01 = packbf(fk.x - bfr(fk.x), fk.y - bfr(fk.y));
            uint32_t l23 = packbf(fk.z - bfr(fk.z), fk.w - bfr(fk.w));
            *(uint2*)&sK[r * QSTR + c]      = make_uint2(h01, h23);
            *(uint2*)&sK[r * QSTR + 64 + c] = make_uint2(l01, l23);
            float4 fv = *(const float4*)(V + goff);
            uint32_t vh01 = packbf(fv.x, fv.y), vh23 = packbf(fv.z, fv.w);
            uint32_t vl01 = packbf(fv.x - bfr(fv.x), fv.y - bfr(fv.y));
            uint32_t vl23 = packbf(fv.z - bfr(fv.z), fv.w - bfr(fv.w));
            *(uint2*)&sV[r * VSTR + c]        = make_uint2(vh01, vh23);
            *(uint2*)&sV[(64 + r) * VSTR + c] = make_uint2(vl01, vl23);
        }
        __syncthreads();

        // ---- S = Qhi*Khi + Qlo*Khi + Qhi*Klo ----
        float sAcc[8][4] = {};
        #pragma unroll
        for (int kg = 0; kg < 4; kg++) {
            uint32_t bF[4][4];
            #pragma unroll
            for (int np = 0; np < 4; np++)
                ldsm_x4(bF[np], sKa + (uint32_t)(((np * 16 + krow) * QSTR + kg * 16 + kc8) * 2));
            #pragma unroll
            for (int np = 0; np < 4; np++) {
                MMA4(sAcc[2 * np],     qF[kg],     bF[np][0], bF[np][1]);
                MMA4(sAcc[2 * np + 1], qF[kg],     bF[np][2], bF[np][3]);
                MMA4(sAcc[2 * np],     qF[4 + kg], bF[np][0], bF[np][1]);
                MMA4(sAcc[2 * np + 1], qF[4 + kg], bF[np][2], bF[np][3]);
            }
        }
        #pragma unroll
        for (int kg = 0; kg < 4; kg++) {
            uint32_t bF[4][4];
            #pragma unroll
            for (int np = 0; np < 4; np++)
                ldsm_x4(bF[np], sKa + (uint32_t)(((np * 16 + krow) * QSTR + 64 + kg * 16 + kc8) * 2));
            #pragma unroll
            for (int np = 0; np < 4; np++) {
                MMA4(sAcc[2 * np],     qF[kg], bF[np][0], bF[np][1]);
                MMA4(sAcc[2 * np + 1], qF[kg], bF[np][2], bF[np][3]);
            }
        }

        // ---- online softmax (log2 domain) ----
        const bool diag = (jt == qt);
        #pragma unroll
        for (int nt = 0; nt < 8; nt++)
            #pragma unroll
            for (int e = 0; e < 4; e++) {
                float v = sAcc[nt][e] * sc;
                if (diag) {
                    int col = nt * 8 + 2 * t + (e & 1);
                    int row = warp * 16 + g + ((e >> 1) << 3);
                    if (col > row) v = -CUDART_INF_F;
                }
                sAcc[nt][e] = v;
            }
        #pragma unroll
        for (int hf = 0; hf < 2; hf++) {
            float mt = -CUDART_INF_F;
            #pragma unroll
            for (int nt = 0; nt < 8; nt++)
                mt = fmaxf(mt, fmaxf(sAcc[nt][2 * hf], sAcc[nt][2 * hf + 1]));
            mt = fmaxf(mt, __shfl_xor_sync(0xffffffffu, mt, 1));
            mt = fmaxf(mt, __shfl_xor_sync(0xffffffffu, mt, 2));
            float mn = fmaxf(mS[hf], mt);
            float alpha = ex2f(mS[hf] - mn);
            mS[hf] = mn;
            float ls = 0.0f;
            #pragma unroll
            for (int nt = 0; nt < 8; nt++) {
                float p0 = ex2f(sAcc[nt][2 * hf]     - mn);
                float p1 = ex2f(sAcc[nt][2 * hf + 1] - mn);
                sAcc[nt][2 * hf] = p0; sAcc[nt][2 * hf + 1] = p1;
                ls += p0 + p1;
            }
            ls += __shfl_xor_sync(0xffffffffu, ls, 1);
            ls += __shfl_xor_sync(0xffffffffu, ls, 2);
            lS[hf] = lS[hf] * alpha + ls;
            #pragma unroll
            for (int nt = 0; nt < 8; nt++) {
                oAcc[nt][2 * hf]     *= alpha;
                oAcc[nt][2 * hf + 1] *= alpha;
            }
        }

        // ---- O += Phi*Vhi + Plo*Vhi + Phi*Vlo ----
        #pragma unroll
        for (int kg = 0; kg < 4; kg++) {
            float p00 = sAcc[2*kg][0], p01 = sAcc[2*kg][1], p02 = sAcc[2*kg][2], p03 = sAcc[2*kg][3];
            float p10 = sAcc[2*kg+1][0], p11 = sAcc[2*kg+1][1], p12 = sAcc[2*kg+1][2], p13 = sAcc[2*kg+1][3];
            uint32_t aH[4] = { packbf(p00, p01), packbf(p02, p03),
                               packbf(p10, p11), packbf(p12, p13) };
            uint32_t aL[4] = { packbf(p00 - bfr(p00), p01 - bfr(p01)),
                               packbf(p02 - bfr(p02), p03 - bfr(p03)),
                               packbf(p10 - bfr(p10), p11 - bfr(p11)),
                               packbf(p12 - bfr(p12), p13 - bfr(p13)) };
            #pragma unroll
            for (int np = 0; np < 4; np++) {
                uint32_t bV[4];
                ldsm_x4_t(bV, sVa + (uint32_t)(((kg * 16 + vrow) * VSTR + np * 16 + vc8) * 2));
                MMA4(oAcc[2 * np],     aH, bV[0], bV[1]);
                MMA4(oAcc[2 * np + 1], aH, bV[2], bV[3]);
                MMA4(oAcc[2 * np],     aL, bV[0], bV[1]);
                MMA4(oAcc[2 * np + 1], aL, bV[2], bV[3]);
            }
        }
        #pragma unroll
        for (int kg = 0; kg < 4; kg++) {
            float p00 = sAcc[2*kg][0], p01 = sAcc[2*kg][1], p02 = sAcc[2*kg][2], p03 = sAcc[2*kg][3];
            float p10 = sAcc[2*kg+1][0], p11 = sAcc[2*kg+1][1], p12 = sAcc[2*kg+1][2], p13 = sAcc[2*kg+1][3];
            uint32_t aH[4] = { packbf(p00, p01), packbf(p02, p03),
                               packbf(p10, p11), packbf(p12, p13) };
            #pragma unroll
            for (int np = 0; np < 4; np++) {
                uint32_t bV[4];
                ldsm_x4_t(bV, sVa + (uint32_t)(((64 + kg * 16 + vrow) * VSTR + np * 16 + vc8) * 2));
                MMA4(oAcc[2 * np],     aH, bV[0], bV[1]);
                MMA4(oAcc[2 * np + 1], aH, bV[2], bV[3]);
            }
        }
    }

    // ---- epilogue ----
    float i0 = 1.0f / lS[0], i1 = 1.0f / lS[1];
    int r0 = qt * 64 + warp * 16 + g;
    #pragma unroll
    for (int nt = 0; nt < 8; nt++) {
        int col = nt * 8 + 2 * t;
        *(float2*)&CTX[base + (size_t)r0 * D_MODEL + col] =
            make_float2(oAcc[nt][0] * i0, oAcc[nt][1] * i0);
        *(float2*)&CTX[base + (size_t)(r0 + 8) * D_MODEL + col] =
            make_float2(oAcc[nt][2] * i1, oAcc[nt][3] * i1);
    }
}

// ---------------- launcher ----------------
extern "C" void kernel_launch(void* const* d_in, const int* in_sizes, int n_in,
                              void* d_out, int out_size)
{
    const float* x  = (const float*)d_in[0];
    const float* Wq = (const float*)d_in[1];
    const float* Wk = (const float*)d_in[2];
    const float* Wv = (const float*)d_in[3];
    const float* Wo = (const float*)d_in[4];
    const float* bo = (const float*)d_in[5];
    float* out = (float*)d_out;

    float *Qp, *Kp, *Vp, *Cp;
    __nv_bfloat16 *xc, *cc, *wq, *wk, *wv, *wo;
    cudaGetSymbolAddress((void**)&Qp, g_Q);
    cudaGetSymbolAddress((void**)&Kp, g_K);
    cudaGetSymbolAddress((void**)&Vp, g_V);
    cudaGetSymbolAddress((void**)&Cp, g_C);
    cudaGetSymbolAddress((void**)&xc, g_xc);
    cudaGetSymbolAddress((void**)&cc, g_cc);
    cudaGetSymbolAddress((void**)&wq, g_wq);
    cudaGetSymbolAddress((void**)&wk, g_wk);
    cudaGetSymbolAddress((void**)&wv, g_wv);
    cudaGetSymbolAddress((void**)&wo, g_wo);

    static bool attr_done = false;
    if (!attr_done) {
        cudaFuncSetAttribute(hgemm3_kernel,
                             cudaFuncAttributeMaxDynamicSharedMemorySize, GEMM_SMEM);
        cudaFuncSetAttribute(attn_tc_kernel,
                             cudaFuncAttributeMaxDynamicSharedMemorySize, ATT_SMEM);
        attr_done = true;
    }

    convert_a_kernel<<<(MTOT * D_MODEL) / 256, 256>>>(x, xc, MTOT);
    dim3 gridW(32, 32), blockW(32, 8);
    convert_w_kernel<<<gridW, blockW>>>(Wq, wq);
    convert_w_kernel<<<gridW, blockW>>>(Wk, wk);
    convert_w_kernel<<<gridW, blockW>>>(Wv, wv);
    convert_w_kernel<<<gridW, blockW>>>(Wo, wo);

    dim3 gridG(D_MODEL / GBN, MTOT / GBM);
    hgemm3_kernel<<<gridG, 256, GEMM_SMEM>>>(xc, wq, nullptr, Qp, MTOT, D_MODEL);
    hgemm3_kernel<<<gridG, 256, GEMM_SMEM>>>(xc, wk, nullptr, Kp, MTOT, D_MODEL);
    hgemm3_kernel<<<gridG, 256, GEMM_SMEM>>>(xc, wv, nullptr, Vp, MTOT, D_MODEL);

    dim3 gridA(SEQ / 64, NHEAD, BATCH);
    attn_tc_kernel<<<gridA, 128, ATT_SMEM>>>(Qp, Kp, Vp, Cp);

    convert_a_kernel<<<(MTOT * D_MODEL) / 256, 256>>>(Cp, cc, MTOT);
    hgemm3_kernel<<<gridG, 256, GEMM_SMEM>>>(cc, wo, bo, out, MTOT, D_MODEL);
}

// round 5
// speedup vs baseline: 2.7187x; 1.0409x over previous
#include <cuda_runtime.h>
#include <cuda_bf16.h>
#include <math_constants.h>
#include <cstdint>

#define D_MODEL 1024
#define SEQ     2048
#define BATCH   4
#define NHEAD   16
#define HDIM    64
#define MTOT    (BATCH * SEQ)
#define KP      (3 * D_MODEL)      // tripled-K for bf16x3 compensation
#define QS      3072               // fused qkv row stride

// -------- scratch (allocation-free: __device__ globals) --------
__device__ __align__(16) __nv_bfloat16 g_xc[(size_t)MTOT * KP];      // [Ahi | Alo | Ahi]
__device__ __align__(16) __nv_bfloat16 g_cc[(size_t)MTOT * KP];      // ctx [hi | lo | hi]
__device__ __align__(16) __nv_bfloat16 g_wqkv[(size_t)QS * KP];      // rows: [Wq cols | Wk | Wv]
__device__ __align__(16) __nv_bfloat16 g_wo[(size_t)D_MODEL * KP];
__device__ __align__(16) __nv_bfloat16 g_hi[(size_t)MTOT * QS];      // qkv hi
__device__ __align__(16) __nv_bfloat16 g_lo[(size_t)MTOT * QS];      // qkv lo

// ---------------- small helpers ----------------
__device__ __forceinline__ float bfr(float x) {
    return __bfloat162float(__float2bfloat16(x));
}
__device__ __forceinline__ uint32_t packbf(float lo, float hi) {
    uint32_t d;
    asm("cvt.rn.bf16x2.f32 %0, %1, %2;" : "=r"(d) : "f"(hi), "f"(lo));
    return d;
}
__device__ __forceinline__ float ex2f(float x) {
    float y; asm("ex2.approx.ftz.f32 %0, %1;" : "=f"(y) : "f"(x)); return y;
}
__device__ __forceinline__ void ldsm_x4(uint32_t* r, uint32_t a) {
    asm volatile("ldmatrix.sync.aligned.m8n8.x4.shared.b16 {%0,%1,%2,%3}, [%4];"
        : "=r"(r[0]), "=r"(r[1]), "=r"(r[2]), "=r"(r[3]) : "r"(a));
}
__device__ __forceinline__ void ldsm_x4_t(uint32_t* r, uint32_t a) {
    asm volatile("ldmatrix.sync.aligned.m8n8.x4.trans.shared.b16 {%0,%1,%2,%3}, [%4];"
        : "=r"(r[0]), "=r"(r[1]), "=r"(r[2]), "=r"(r[3]) : "r"(a));
}
__device__ __forceinline__ void cp_async16(uint32_t smem, const void* gptr) {
    asm volatile("cp.async.cg.shared.global [%0], [%1], 16;\n"
                 :: "r"(smem), "l"(gptr) : "memory");
}
__device__ __forceinline__ uint32_t smem_u32(const void* p) {
    return (uint32_t)__cvta_generic_to_shared(p);
}

#define MMA4(d, a, b0, b1)                                                    \
    asm volatile(                                                             \
        "mma.sync.aligned.m16n8k16.row.col.f32.bf16.bf16.f32 "                \
        "{%0,%1,%2,%3}, {%4,%5,%6,%7}, {%8,%9}, {%0,%1,%2,%3};"               \
        : "+f"(d[0]), "+f"(d[1]), "+f"(d[2]), "+f"(d[3])                      \
        : "r"(a[0]), "r"(a[1]), "r"(a[2]), "r"(a[3]), "r"(b0), "r"(b1))

// ---------------- conversion kernels ----------------
__global__ void convert_a_kernel(const float* __restrict__ X,
                                 __nv_bfloat16* __restrict__ O, int M)
{
    size_t i = (size_t)blockIdx.x * blockDim.x + threadIdx.x;
    if (i >= (size_t)M * D_MODEL) return;
    int m = (int)(i >> 10), k = (int)(i & 1023);
    float x = X[i];
    __nv_bfloat16 hi = __float2bfloat16(x);
    __nv_bfloat16 lo = __float2bfloat16(x - __bfloat162float(hi));
    __nv_bfloat16* row = O + (size_t)m * KP;
    row[k] = hi; row[k + D_MODEL] = lo; row[k + 2 * D_MODEL] = hi;
}

// Weight transpose via smem tile; O already offset to the destination row block.
__global__ void convert_w_kernel(const float* __restrict__ W,
                                 __nv_bfloat16* __restrict__ O)
{
    __shared__ float tile[32][33];
    const int n0 = blockIdx.x * 32, k0 = blockIdx.y * 32;
    const int tx = threadIdx.x, ty = threadIdx.y;      // (32, 8)
    #pragma unroll
    for (int i = 0; i < 4; i++)
        tile[ty + 8 * i][tx] = W[(size_t)(k0 + ty + 8 * i) * D_MODEL + n0 + tx];
    __syncthreads();
    #pragma unroll
    for (int i = 0; i < 4; i++) {
        int r = ty + 8 * i;
        float w = tile[tx][r];
        __nv_bfloat16 hi = __float2bfloat16(w);
        __nv_bfloat16 lo = __float2bfloat16(w - __bfloat162float(hi));
        __nv_bfloat16* row = O + (size_t)(n0 + r) * KP;
        row[k0 + tx] = hi;
        row[D_MODEL + k0 + tx] = hi;
        row[2 * D_MODEL + k0 + tx] = lo;
    }
}

// ---------------- mma.sync GEMM, ldmatrix mainloop, 3-stage cp.async ----------------
// C[M,N] = A[M,KP] @ Bt[N,KP]^T.  mode 0: fp32 C + bias.  mode 1: bf16 hi/lo out.
#define GBM 128
#define GBN 128
#define SSTR 72
#define MST  3
#define TILE_E (GBM * SSTR)                     // elems per stage per matrix
#define G_SMEM (2 * MST * TILE_E * 2)           // 110592 bytes
#define G_NIT  (KP / 64)                        // 48

__global__ __launch_bounds__(256) void mgemm_kernel(
    const __nv_bfloat16* __restrict__ A,
    const __nv_bfloat16* __restrict__ Bt,
    const float* __restrict__ bias,
    float* __restrict__ Cf,
    __nv_bfloat16* __restrict__ Chi,
    __nv_bfloat16* __restrict__ Clo,
    int N, int mode)
{
    extern __shared__ __nv_bfloat16 sm[];
    __nv_bfloat16* sA = sm;
    __nv_bfloat16* sB = sm + MST * TILE_E;

    const int tid  = threadIdx.x;
    const int warp = tid >> 5, lane = tid & 31;
    const int bm = blockIdx.y * GBM;
    const int bn = blockIdx.x * GBN;
    const int wm = warp >> 1, wn = warp & 1;
    const int m_base = wm * 32, n_base = wn * 64;
    const int g = lane >> 2, t = lane & 3;
    const int lrow = lane & 15, lcol = (lane >> 4) << 3;  // ldmatrix addressing

    const uint32_t sA0 = smem_u32(sA);
    const uint32_t sB0 = smem_u32(sB);

    float acc[2][8][4] = {};

    auto issue = [&](int it) {
        const int s = it % MST;
        const int k0 = it * 64;
        #pragma unroll
        for (int i = 0; i < 4; i++) {
            int idx = tid + i * 256;
            int row = idx >> 3, c16 = idx & 7;
            uint32_t off = (uint32_t)((s * GBM + row) * SSTR + c16 * 8) * 2;
            cp_async16(sA0 + off, A + (size_t)(bm + row) * KP + k0 + c16 * 8);
            cp_async16(sB0 + off, Bt + (size_t)(bn + row) * KP + k0 + c16 * 8);
        }
        asm volatile("cp.async.commit_group;" ::: "memory");
    };

    issue(0); issue(1);

    for (int it = 0; it < G_NIT; ++it) {
        if (it == G_NIT - 1) asm volatile("cp.async.wait_group 0;" ::: "memory");
        else                 asm volatile("cp.async.wait_group 1;" ::: "memory");
        __syncthreads();
        if (it + 2 < G_NIT) issue(it + 2);

        const uint32_t aS = sA0 + (uint32_t)((it % MST) * TILE_E) * 2;
        const uint32_t bS = sB0 + (uint32_t)((it % MST) * TILE_E) * 2;

        #pragma unroll
        for (int ks = 0; ks < 4; ks++) {
            const uint32_t kb = (uint32_t)(ks * 32 + lcol * 2);  // byte col within row
            uint32_t aF[2][4], bF[4][4];
            #pragma unroll
            for (int mt = 0; mt < 2; mt++)
                ldsm_x4(aF[mt], aS + (uint32_t)((m_base + mt * 16 + lrow) * SSTR) * 2 + kb);
            #pragma unroll
            for (int nt = 0; nt < 4; nt++)
                ldsm_x4(bF[nt], bS + (uint32_t)((n_base + nt * 16 + lrow) * SSTR) * 2 + kb);
            #pragma unroll
            for (int mt = 0; mt < 2; mt++)
                #pragma unroll
                for (int nt = 0; nt < 4; nt++) {
                    MMA4(acc[mt][2 * nt],     aF[mt], bF[nt][0], bF[nt][2]);
                    MMA4(acc[mt][2 * nt + 1], aF[mt], bF[nt][1], bF[nt][3]);
                }
        }
    }

    if (mode == 0) {
        #pragma unroll
        for (int mt = 0; mt < 2; mt++) {
            int r0 = bm + m_base + mt * 16 + g;
            #pragma unroll
            for (int nt = 0; nt < 8; nt++) {
                int col = bn + n_base + nt * 8 + 2 * t;
                float b0 = bias[col], b1 = bias[col + 1];
                *(float2*)&Cf[(size_t)r0 * N + col] =
                    make_float2(acc[mt][nt][0] + b0, acc[mt][nt][1] + b1);
                *(float2*)&Cf[(size_t)(r0 + 8) * N + col] =
                    make_float2(acc[mt][nt][2] + b0, acc[mt][nt][3] + b1);
            }
        }
    } else {
        #pragma unroll
        for (int mt = 0; mt < 2; mt++) {
            int r0 = bm + m_base + mt * 16 + g;
            #pragma unroll
            for (int nt = 0; nt < 8; nt++) {
                int col = bn + n_base + nt * 8 + 2 * t;
                float v0 = acc[mt][nt][0], v1 = acc[mt][nt][1];
                float v2 = acc[mt][nt][2], v3 = acc[mt][nt][3];
                *(uint32_t*)&Chi[(size_t)r0 * N + col]       = packbf(v0, v1);
                *(uint32_t*)&Clo[(size_t)r0 * N + col]       =
                    packbf(v0 - bfr(v0), v1 - bfr(v1));
                *(uint32_t*)&Chi[(size_t)(r0 + 8) * N + col] = packbf(v2, v3);
                *(uint32_t*)&Clo[(size_t)(r0 + 8) * N + col] =
                    packbf(v2 - bfr(v2), v3 - bfr(v3));
            }
        }
    }
}

// ---------------- flash attention: bf16 hi/lo inputs, double-buffered K/V ----------------
// smem: sQ[64][136] (hi|lo), sK[2][64][136] (hi|lo), sV[2][128][72] (hi rows 0-63, lo 64-127)
#define QSTR 136
#define VSTR 72
#define KBUF (64 * QSTR)
#define VBUF (128 * VSTR)
#define ATT_SMEM ((64 * QSTR + 2 * KBUF + 2 * VBUF) * 2)   // 89088 bytes

__global__ __launch_bounds__(128) void attn_tc_kernel(
    const __nv_bfloat16* __restrict__ HI,
    const __nv_bfloat16* __restrict__ LO,
    __nv_bfloat16* __restrict__ CC)
{
    extern __shared__ __nv_bfloat16 sm_at[];
    __nv_bfloat16* sQ = sm_at;
    __nv_bfloat16* sK = sQ + 64 * QSTR;
    __nv_bfloat16* sV = sK + 2 * KBUF;

    const int tid  = threadIdx.x;
    const int warp = tid >> 5, lane = tid & 31;
    const int g = lane >> 2, t = lane & 3;
    const int qt = blockIdx.x, h = blockIdx.y, b = blockIdx.z;
    const int hoff = h * HDIM;
    const size_t mrow0 = (size_t)b * SEQ;    // global row base of this batch

    const uint32_t sQa = smem_u32(sQ);
    const uint32_t sKa = smem_u32(sK);
    const uint32_t sVa = smem_u32(sV);

    // ---- Q tile: hi -> cols 0-63, lo -> cols 64-127 ----
    #pragma unroll
    for (int u = 0; u < 8; u++) {
        int idx = tid + u * 128;
        int r = idx >> 4, cc = idx & 15;
        const __nv_bfloat16* src = (cc < 8 ? HI : LO)
            + (mrow0 + qt * 64 + r) * QS + hoff + (cc & 7) * 8;
        cp_async16(sQa + (uint32_t)(r * QSTR + (cc < 8 ? 0 : 64) + (cc & 7) * 8) * 2, src);
    }

    auto issue_kv = [&](int jt, int buf) {
        #pragma unroll
        for (int u = 0; u < 8; u++) {      // K tile
            int idx = tid + u * 128;
            int r = idx >> 4, cc = idx & 15;
            const __nv_bfloat16* src = (cc < 8 ? HI : LO)
                + (mrow0 + jt * 64 + r) * QS + 1024 + hoff + (cc & 7) * 8;
            cp_async16(sKa + (uint32_t)(buf * KBUF + r * QSTR
                       + (cc < 8 ? 0 : 64) + (cc & 7) * 8) * 2, src);
        }
        #pragma unroll
        for (int u = 0; u < 8; u++) {      // V tile
            int idx = tid + u * 128;
            int r = idx >> 4, cc = idx & 15;
            const __nv_bfloat16* src = (cc < 8 ? HI : LO)
                + (mrow0 + jt * 64 + r) * QS + 2048 + hoff + (cc & 7) * 8;
            cp_async16(sVa + (uint32_t)(buf * VBUF + (cc < 8 ? r : 64 + r) * VSTR
                       + (cc & 7) * 8) * 2, src);
        }
        asm volatile("cp.async.commit_group;" ::: "memory");
    };

    issue_kv(0, 0);   // one group: sQ + kv0

    uint32_t qF[8][4];
    float oAcc[8][4] = {};
    float mS[2] = {-CUDART_INF_F, -CUDART_INF_F};
    float lS[2] = {0.0f, 0.0f};

    const int krow = (lane & 7) | ((lane >> 4) << 3);
    const int kc8  = ((lane >> 3) & 1) << 3;
    const int vrow = lane & 15;
    const int vc8  = (lane >> 4) << 3;
    const float sc = 0.18033688011112042f;              // 0.125 * log2(e)

    for (int jt = 0; jt <= qt; jt++) {
        const int buf = jt & 1;
        asm volatile("cp.async.wait_group 0;" ::: "memory");
        __syncthreads();
        if (jt == 0) {                     // Q fragments once
            int rr = warp * 16 + (lane & 15);
            int cc = (lane >> 4) << 3;
            #pragma unroll
            for (int kg = 0; kg < 8; kg++)
                ldsm_x4(qF[kg], sQa + (uint32_t)((rr * QSTR + kg * 16 + cc) * 2));
        }
        if (jt < qt) issue_kv(jt + 1, buf ^ 1);

        const uint32_t kS = sKa + (uint32_t)(buf * KBUF) * 2;
        const uint32_t vS = sVa + (uint32_t)(buf * VBUF) * 2;

        // ---- S = Qhi*Khi + Qlo*Khi + Qhi*Klo ----
        float sAcc[8][4] = {};
        #pragma unroll
        for (int kg = 0; kg < 4; kg++) {
            uint32_t bF[4][4];
            #pragma unroll
            for (int np = 0; np < 4; np++)
                ldsm_x4(bF[np], kS + (uint32_t)(((np * 16 + krow) * QSTR + kg * 16 + kc8) * 2));
            #pragma unroll
            for (int np = 0; np < 4; np++) {
                MMA4(sAcc[2 * np],     qF[kg],     bF[np][0], bF[np][1]);
                MMA4(sAcc[2 * np + 1], qF[kg],     bF[np][2], bF[np][3]);
                MMA4(sAcc[2 * np],     qF[4 + kg], bF[np][0], bF[np][1]);
                MMA4(sAcc[2 * np + 1], qF[4 + kg], bF[np][2], bF[np][3]);
            }
        }
        #pragma unroll
        for (int kg = 0; kg < 4; kg++) {
            uint32_t bF[4][4];
            #pragma unroll
            for (int np = 0; np < 4; np++)
                ldsm_x4(bF[np], kS + (uint32_t)(((np * 16 + krow) * QSTR + 64 + kg * 16 + kc8) * 2));
            #pragma unroll
            for (int np = 0; np < 4; np++) {
                MMA4(sAcc[2 * np],     qF[kg], bF[np][0], bF[np][1]);
                MMA4(sAcc[2 * np + 1], qF[kg], bF[np][2], bF[np][3]);
            }
        }

        // ---- online softmax ----
        const bool diag = (jt == qt);
        #pragma unroll
        for (int nt = 0; nt < 8; nt++)
            #pragma unroll
            for (int e = 0; e < 4; e++) {
                float v = sAcc[nt][e] * sc;
                if (diag) {
                    int col = nt * 8 + 2 * t + (e & 1);
                    int row = warp * 16 + g + ((e >> 1) << 3);
                    if (col > row) v = -CUDART_INF_F;
                }
                sAcc[nt][e] = v;
            }
        #pragma unroll
        for (int hf = 0; hf < 2; hf++) {
            float mt = -CUDART_INF_F;
            #pragma unroll
            for (int nt = 0; nt < 8; nt++)
                mt = fmaxf(mt, fmaxf(sAcc[nt][2 * hf], sAcc[nt][2 * hf + 1]));
            mt = fmaxf(mt, __shfl_xor_sync(0xffffffffu, mt, 1));
            mt = fmaxf(mt, __shfl_xor_sync(0xffffffffu, mt, 2));
            float mn = fmaxf(mS[hf], mt);
            float alpha = ex2f(mS[hf] - mn);
            mS[hf] = mn;
            float ls = 0.0f;
            #pragma unroll
            for (int nt = 0; nt < 8; nt++) {
                float p0 = ex2f(sAcc[nt][2 * hf]     - mn);
                float p1 = ex2f(sAcc[nt][2 * hf + 1] - mn);
                sAcc[nt][2 * hf] = p0; sAcc[nt][2 * hf + 1] = p1;
                ls += p0 + p1;
            }
            ls += __shfl_xor_sync(0xffffffffu, ls, 1);
            ls += __shfl_xor_sync(0xffffffffu, ls, 2);
            lS[hf] = lS[hf] * alpha + ls;
            #pragma unroll
            for (int nt = 0; nt < 8; nt++) {
                oAcc[nt][2 * hf]     *= alpha;
                oAcc[nt][2 * hf + 1] *= alpha;
            }
        }

        // ---- O += Phi*Vhi + Plo*Vhi + Phi*Vlo ----
        #pragma unroll
        for (int kg = 0; kg < 4; kg++) {
            float p00 = sAcc[2*kg][0], p01 = sAcc[2*kg][1], p02 = sAcc[2*kg][2], p03 = sAcc[2*kg][3];
            float p10 = sAcc[2*kg+1][0], p11 = sAcc[2*kg+1][1], p12 = sAcc[2*kg+1][2], p13 = sAcc[2*kg+1][3];
            uint32_t aH[4] = { packbf(p00, p01), packbf(p02, p03),
                               packbf(p10, p11), packbf(p12, p13) };
            uint32_t aL[4] = { packbf(p00 - bfr(p00), p01 - bfr(p01)),
                               packbf(p02 - bfr(p02), p03 - bfr(p03)),
                               packbf(p10 - bfr(p10), p11 - bfr(p11)),
                               packbf(p12 - bfr(p12), p13 - bfr(p13)) };
            #pragma unroll
            for (int np = 0; np < 4; np++) {
                uint32_t bV[4];
                ldsm_x4_t(bV, vS + (uint32_t)(((kg * 16 + vrow) * VSTR + np * 16 + vc8) * 2));
                MMA4(oAcc[2 * np],     aH, bV[0], bV[1]);
                MMA4(oAcc[2 * np + 1], aH, bV[2], bV[3]);
                MMA4(oAcc[2 * np],     aL, bV[0], bV[1]);
                MMA4(oAcc[2 * np + 1], aL, bV[2], bV[3]);
            }
        }
        #pragma unroll
        for (int kg = 0; kg < 4; kg++) {
            float p00 = sAcc[2*kg][0], p01 = sAcc[2*kg][1], p02 = sAcc[2*kg][2], p03 = sAcc[2*kg][3];
            float p10 = sAcc[2*kg+1][0], p11 = sAcc[2*kg+1][1], p12 = sAcc[2*kg+1][2], p13 = sAcc[2*kg+1][3];
            uint32_t aH[4] = { packbf(p00, p01), packbf(p02, p03),
                               packbf(p10, p11), packbf(p12, p13) };
            #pragma unroll
            for (int np = 0; np < 4; np++) {
                uint32_t bV[4];
                ldsm_x4_t(bV, vS + (uint32_t)(((64 + kg * 16 + vrow) * VSTR + np * 16 + vc8) * 2));
                MMA4(oAcc[2 * np],     aH, bV[0], bV[1]);
                MMA4(oAcc[2 * np + 1], aH, bV[2], bV[3]);
            }
        }
    }

    // ---- epilogue: write ctx straight into [hi | lo | hi] bf16 layout ----
    float i0 = 1.0f / lS[0], i1 = 1.0f / lS[1];
    size_t r0 = mrow0 + qt * 64 + warp * 16 + g;
    #pragma unroll
    for (int nt = 0; nt < 8; nt++) {
        int col = hoff + nt * 8 + 2 * t;
        float v0 = oAcc[nt][0] * i0, v1 = oAcc[nt][1] * i0;
        float v2 = oAcc[nt][2] * i1, v3 = oAcc[nt][3] * i1;
        __nv_bfloat16* row_a = CC + r0 * KP;
        __nv_bfloat16* row_b = CC + (r0 + 8) * KP;
        uint32_t h01 = packbf(v0, v1), h23 = packbf(v2, v3);
        *(uint32_t*)&row_a[col]               = h01;
        *(uint32_t*)&row_a[D_MODEL + col]     = packbf(v0 - bfr(v0), v1 - bfr(v1));
        *(uint32_t*)&row_a[2 * D_MODEL + col] = h01;
        *(uint32_t*)&row_b[col]               = h23;
        *(uint32_t*)&row_b[D_MODEL + col]     = packbf(v2 - bfr(v2), v3 - bfr(v3));
        *(uint32_t*)&row_b[2 * D_MODEL + col] = h23;
    }
}

// ---------------- launcher ----------------
extern "C" void kernel_launch(void* const* d_in, const int* in_sizes, int n_in,
                              void* d_out, int out_size)
{
    const float* x  = (const float*)d_in[0];
    const float* Wq = (const float*)d_in[1];
    const float* Wk = (const float*)d_in[2];
    const float* Wv = (const float*)d_in[3];
    const float* Wo = (const float*)d_in[4];
    const float* bo = (const float*)d_in[5];
    float* out = (float*)d_out;

    __nv_bfloat16 *xc, *cc, *wqkv, *wo, *hi, *lo;
    cudaGetSymbolAddress((void**)&xc, g_xc);
    cudaGetSymbolAddress((void**)&cc, g_cc);
    cudaGetSymbolAddress((void**)&wqkv, g_wqkv);
    cudaGetSymbolAddress((void**)&wo, g_wo);
    cudaGetSymbolAddress((void**)&hi, g_hi);
    cudaGetSymbolAddress((void**)&lo, g_lo);

    static bool attr_done = false;
    if (!attr_done) {
        cudaFuncSetAttribute(mgemm_kernel,
                             cudaFuncAttributeMaxDynamicSharedMemorySize, G_SMEM);
        cudaFuncSetAttribute(attn_tc_kernel,
                             cudaFuncAttributeMaxDynamicSharedMemorySize, ATT_SMEM);
        attr_done = true;
    }

    convert_a_kernel<<<(MTOT * D_MODEL) / 256, 256>>>(x, xc, MTOT);
    dim3 gridW(32, 32), blockW(32, 8);
    convert_w_kernel<<<gridW, blockW>>>(Wq, wqkv);
    convert_w_kernel<<<gridW, blockW>>>(Wk, wqkv + (size_t)1024 * KP);
    convert_w_kernel<<<gridW, blockW>>>(Wv, wqkv + (size_t)2048 * KP);
    convert_w_kernel<<<gridW, blockW>>>(Wo, wo);

    // fused QKV GEMM: N = 3072, bf16 hi/lo epilogue
    dim3 gridQKV(QS / GBN, MTOT / GBM);      // (24, 64)
    mgemm_kernel<<<gridQKV, 256, G_SMEM>>>(xc, wqkv, nullptr,
                                           nullptr, hi, lo, QS, 1);

    dim3 gridA(SEQ / 64, NHEAD, BATCH);      // (32, 16, 4)
    attn_tc_kernel<<<gridA, 128, ATT_SMEM>>>(hi, lo, cc);

    // output GEMM: fp32 + bias
    dim3 gridO(D_MODEL / GBN, MTOT / GBM);   // (8, 64)
    mgemm_kernel<<<gridO, 256, G_SMEM>>>(cc, wo, bo,
                                         out, nullptr, nullptr, D_MODEL, 0);
}

// round 6
// speedup vs baseline: 2.7644x; 1.0168x over previous
#include <cuda_runtime.h>
#include <cuda_bf16.h>
#include <math_constants.h>
#include <cstdint>

#define D_MODEL 1024
#define SEQ     2048
#define BATCH   4
#define NHEAD   16
#define HDIM    64
#define MTOT    (BATCH * SEQ)
#define KD      1024               // true reduction dim
#define QS      3072               // fused qkv row stride

// -------- scratch (allocation-free: __device__ globals) --------
__device__ __align__(16) __nv_bfloat16 g_xhi[(size_t)MTOT * KD];
__device__ __align__(16) __nv_bfloat16 g_xlo[(size_t)MTOT * KD];
__device__ __align__(16) __nv_bfloat16 g_whi[(size_t)QS * KD];     // [Wq|Wk|Wv] transposed hi
__device__ __align__(16) __nv_bfloat16 g_wlo[(size_t)QS * KD];
__device__ __align__(16) __nv_bfloat16 g_wohi[(size_t)D_MODEL * KD];
__device__ __align__(16) __nv_bfloat16 g_wolo[(size_t)D_MODEL * KD];
__device__ __align__(16) __nv_bfloat16 g_hi[(size_t)MTOT * QS];    // qkv hi
__device__ __align__(16) __nv_bfloat16 g_lo[(size_t)MTOT * QS];    // qkv lo
__device__ __align__(16) __nv_bfloat16 g_chi[(size_t)MTOT * D_MODEL];
__device__ __align__(16) __nv_bfloat16 g_clo[(size_t)MTOT * D_MODEL];

// ---------------- small helpers ----------------
__device__ __forceinline__ float bfr(float x) {
    return __bfloat162float(__float2bfloat16(x));
}
__device__ __forceinline__ uint32_t packbf(float lo, float hi) {
    uint32_t d;
    asm("cvt.rn.bf16x2.f32 %0, %1, %2;" : "=r"(d) : "f"(hi), "f"(lo));
    return d;
}
__device__ __forceinline__ float ex2f(float x) {
    float y; asm("ex2.approx.ftz.f32 %0, %1;" : "=f"(y) : "f"(x)); return y;
}
__device__ __forceinline__ void ldsm_x4(uint32_t* r, uint32_t a) {
    asm volatile("ldmatrix.sync.aligned.m8n8.x4.shared.b16 {%0,%1,%2,%3}, [%4];"
        : "=r"(r[0]), "=r"(r[1]), "=r"(r[2]), "=r"(r[3]) : "r"(a));
}
__device__ __forceinline__ void ldsm_x4_t(uint32_t* r, uint32_t a) {
    asm volatile("ldmatrix.sync.aligned.m8n8.x4.trans.shared.b16 {%0,%1,%2,%3}, [%4];"
        : "=r"(r[0]), "=r"(r[1]), "=r"(r[2]), "=r"(r[3]) : "r"(a));
}
__device__ __forceinline__ void cp_async16(uint32_t smem, const void* gptr) {
    asm volatile("cp.async.cg.shared.global [%0], [%1], 16;\n"
                 :: "r"(smem), "l"(gptr) : "memory");
}
__device__ __forceinline__ uint32_t smem_u32(const void* p) {
    return (uint32_t)__cvta_generic_to_shared(p);
}

#define MMA4(d, a, b0, b1)                                                    \
    asm volatile(                                                             \
        "mma.sync.aligned.m16n8k16.row.col.f32.bf16.bf16.f32 "                \
        "{%0,%1,%2,%3}, {%4,%5,%6,%7}, {%8,%9}, {%0,%1,%2,%3};"               \
        : "+f"(d[0]), "+f"(d[1]), "+f"(d[2]), "+f"(d[3])                      \
        : "r"(a[0]), "r"(a[1]), "r"(a[2]), "r"(a[3]), "r"(b0), "r"(b1))

// ---------------- conversion kernels ----------------
__global__ void convert_a_kernel(const float* __restrict__ X,
                                 __nv_bfloat16* __restrict__ Ohi,
                                 __nv_bfloat16* __restrict__ Olo, int M)
{
    size_t i = (size_t)blockIdx.x * blockDim.x + threadIdx.x;
    if (i >= (size_t)M * KD) return;
    float x = X[i];
    __nv_bfloat16 hi = __float2bfloat16(x);
    Ohi[i] = hi;
    Olo[i] = __float2bfloat16(x - __bfloat162float(hi));
}

// Weight transpose + split via smem tile; O pointers pre-offset to row block.
__global__ void convert_w_kernel(const float* __restrict__ W,
                                 __nv_bfloat16* __restrict__ Ohi,
                                 __nv_bfloat16* __restrict__ Olo)
{
    __shared__ float tile[32][33];
    const int n0 = blockIdx.x * 32, k0 = blockIdx.y * 32;
    const int tx = threadIdx.x, ty = threadIdx.y;      // (32, 8)
    #pragma unroll
    for (int i = 0; i < 4; i++)
        tile[ty + 8 * i][tx] = W[(size_t)(k0 + ty + 8 * i) * D_MODEL + n0 + tx];
    __syncthreads();
    #pragma unroll
    for (int i = 0; i < 4; i++) {
        int r = ty + 8 * i;
        float w = tile[tx][r];
        __nv_bfloat16 hi = __float2bfloat16(w);
        size_t o = (size_t)(n0 + r) * KD + k0 + tx;
        Ohi[o] = hi;
        Olo[o] = __float2bfloat16(w - __bfloat162float(hi));
    }
}

// ---------------- mma.sync GEMM with register-level bf16x3 compensation ----------------
// C[M,N] = (Ahi+Alo)[M,K] @ (Bhi+Blo)t[N,K]^T  via AhiBhi + AloBhi + AhiBlo.
// smem tiles: [stage][128 rows][72], row = 32 hi cols | 32 lo cols | pad.
#define GBM 128
#define GBN 128
#define SSTR 72
#define MST  3
#define TILE_E (GBM * SSTR)
#define G_SMEM (2 * MST * TILE_E * 2)           // 110592 bytes
#define G_NIT  (KD / 32)                        // 32 chunks

__global__ __launch_bounds__(256, 2) void mgemm_kernel(
    const __nv_bfloat16* __restrict__ Ahi, const __nv_bfloat16* __restrict__ Alo,
    const __nv_bfloat16* __restrict__ Bhi, const __nv_bfloat16* __restrict__ Blo,
    const float* __restrict__ bias,
    float* __restrict__ Cf,
    __nv_bfloat16* __restrict__ Chi, __nv_bfloat16* __restrict__ Clo,
    int N, int mode)
{
    extern __shared__ __nv_bfloat16 sm[];
    __nv_bfloat16* sA = sm;
    __nv_bfloat16* sB = sm + MST * TILE_E;

    const int tid  = threadIdx.x;
    const int warp = tid >> 5, lane = tid & 31;
    const int bm = blockIdx.y * GBM;
    const int bn = blockIdx.x * GBN;
    const int wm = warp >> 1, wn = warp & 1;
    const int m_base = wm * 32, n_base = wn * 64;
    const int g = lane >> 2, t = lane & 3;
    const int lrow = lane & 15, lcolb = ((lane >> 4) << 3) * 2;  // ldmatrix byte col

    const uint32_t sA0 = smem_u32(sA);
    const uint32_t sB0 = smem_u32(sB);

    float acc[2][8][4] = {};

    auto issue = [&](int it) {
        const int s = it % MST;
        const int k0 = it * 32;
        #pragma unroll
        for (int i = 0; i < 2; i++) {
            int idx = tid + i * 256;
            int row = idx >> 2, c16 = idx & 3;             // 4 x 16B = 32 hi cols
            uint32_t o = (uint32_t)((s * GBM + row) * SSTR + c16 * 8) * 2;
            size_t ga = (size_t)(bm + row) * KD + k0 + c16 * 8;
            size_t gb = (size_t)(bn + row) * KD + k0 + c16 * 8;
            cp_async16(sA0 + o,      Ahi + ga);
            cp_async16(sA0 + o + 64, Alo + ga);            // lo at elem col 32
            cp_async16(sB0 + o,      Bhi + gb);
            cp_async16(sB0 + o + 64, Blo + gb);
        }
        asm volatile("cp.async.commit_group;" ::: "memory");
    };

    issue(0); issue(1);

    for (int it = 0; it < G_NIT; ++it) {
        if (it == G_NIT - 1) asm volatile("cp.async.wait_group 0;" ::: "memory");
        else                 asm volatile("cp.async.wait_group 1;" ::: "memory");
        __syncthreads();
        if (it + 2 < G_NIT) issue(it + 2);

        const uint32_t aS = sA0 + (uint32_t)((it % MST) * TILE_E) * 2;
        const uint32_t bS = sB0 + (uint32_t)((it % MST) * TILE_E) * 2;

        #pragma unroll
        for (int ks = 0; ks < 2; ks++) {
            const uint32_t kb = (uint32_t)(ks * 32) + lcolb;   // hi bytes 0-63
            uint32_t aH[2][4], aL[2][4], bF[4][4];
            #pragma unroll
            for (int mt = 0; mt < 2; mt++) {
                uint32_t ra = aS + (uint32_t)((m_base + mt * 16 + lrow) * SSTR) * 2;
                ldsm_x4(aH[mt], ra + kb);
                ldsm_x4(aL[mt], ra + kb + 64);                 // lo bytes 64-127
            }
            #pragma unroll
            for (int nt = 0; nt < 4; nt++)
                ldsm_x4(bF[nt], bS + (uint32_t)((n_base + nt * 16 + lrow) * SSTR) * 2 + kb);
            #pragma unroll
            for (int mt = 0; mt < 2; mt++)
                #pragma unroll
                for (int nt = 0; nt < 4; nt++) {
                    MMA4(acc[mt][2 * nt],     aH[mt], bF[nt][0], bF[nt][2]);
                    MMA4(acc[mt][2 * nt + 1], aH[mt], bF[nt][1], bF[nt][3]);
                    MMA4(acc[mt][2 * nt],     aL[mt], bF[nt][0], bF[nt][2]);
                    MMA4(acc[mt][2 * nt + 1], aL[mt], bF[nt][1], bF[nt][3]);
                }
            #pragma unroll
            for (int nt = 0; nt < 4; nt++)                     // reload as Blo
                ldsm_x4(bF[nt], bS + (uint32_t)((n_base + nt * 16 + lrow) * SSTR) * 2 + kb + 64);
            #pragma unroll
            for (int mt = 0; mt < 2; mt++)
                #pragma unroll
                for (int nt = 0; nt < 4; nt++) {
                    MMA4(acc[mt][2 * nt],     aH[mt], bF[nt][0], bF[nt][2]);
                    MMA4(acc[mt][2 * nt + 1], aH[mt], bF[nt][1], bF[nt][3]);
                }
        }
    }

    if (mode == 0) {
        #pragma unroll
        for (int mt = 0; mt < 2; mt++) {
            int r0 = bm + m_base + mt * 16 + g;
            #pragma unroll
            for (int nt = 0; nt < 8; nt++) {
                int col = bn + n_base + nt * 8 + 2 * t;
                float b0 = bias[col], b1 = bias[col + 1];
                *(float2*)&Cf[(size_t)r0 * N + col] =
                    make_float2(acc[mt][nt][0] + b0, acc[mt][nt][1] + b1);
                *(float2*)&Cf[(size_t)(r0 + 8) * N + col] =
                    make_float2(acc[mt][nt][2] + b0, acc[mt][nt][3] + b1);
            }
        }
    } else {
        #pragma unroll
        for (int mt = 0; mt < 2; mt++) {
            int r0 = bm + m_base + mt * 16 + g;
            #pragma unroll
            for (int nt = 0; nt < 8; nt++) {
                int col = bn + n_base + nt * 8 + 2 * t;
                float v0 = acc[mt][nt][0], v1 = acc[mt][nt][1];
                float v2 = acc[mt][nt][2], v3 = acc[mt][nt][3];
                *(uint32_t*)&Chi[(size_t)r0 * N + col]       = packbf(v0, v1);
                *(uint32_t*)&Clo[(size_t)r0 * N + col]       =
                    packbf(v0 - bfr(v0), v1 - bfr(v1));
                *(uint32_t*)&Chi[(size_t)(r0 + 8) * N + col] = packbf(v2, v3);
                *(uint32_t*)&Clo[(size_t)(r0 + 8) * N + col] =
                    packbf(v2 - bfr(v2), v3 - bfr(v3));
            }
        }
    }
}

// ---------------- flash attention: bf16 hi/lo inputs, double-buffered K/V ----------------
#define QSTR 136
#define VSTR 72
#define KBUF (64 * QSTR)
#define VBUF (128 * VSTR)
#define ATT_SMEM ((64 * QSTR + 2 * KBUF + 2 * VBUF) * 2)   // 89088 bytes

__global__ __launch_bounds__(128) void attn_tc_kernel(
    const __nv_bfloat16* __restrict__ HI,
    const __nv_bfloat16* __restrict__ LO,
    __nv_bfloat16* __restrict__ CChi,
    __nv_bfloat16* __restrict__ CClo)
{
    extern __shared__ __nv_bfloat16 sm_at[];
    __nv_bfloat16* sQ = sm_at;
    __nv_bfloat16* sK = sQ + 64 * QSTR;
    __nv_bfloat16* sV = sK + 2 * KBUF;

    const int tid  = threadIdx.x;
    const int warp = tid >> 5, lane = tid & 31;
    const int g = lane >> 2, t = lane & 3;
    const int qt = blockIdx.x, h = blockIdx.y, b = blockIdx.z;
    const int hoff = h * HDIM;
    const size_t mrow0 = (size_t)b * SEQ;

    const uint32_t sQa = smem_u32(sQ);
    const uint32_t sKa = smem_u32(sK);
    const uint32_t sVa = smem_u32(sV);

    #pragma unroll
    for (int u = 0; u < 8; u++) {
        int idx = tid + u * 128;
        int r = idx >> 4, cc = idx & 15;
        const __nv_bfloat16* src = (cc < 8 ? HI : LO)
            + (mrow0 + qt * 64 + r) * QS + hoff + (cc & 7) * 8;
        cp_async16(sQa + (uint32_t)(r * QSTR + (cc < 8 ? 0 : 64) + (cc & 7) * 8) * 2, src);
    }

    auto issue_kv = [&](int jt, int buf) {
        #pragma unroll
        for (int u = 0; u < 8; u++) {
            int idx = tid + u * 128;
            int r = idx >> 4, cc = idx & 15;
            const __nv_bfloat16* src = (cc < 8 ? HI : LO)
                + (mrow0 + jt * 64 + r) * QS + 1024 + hoff + (cc & 7) * 8;
            cp_async16(sKa + (uint32_t)(buf * KBUF + r * QSTR
                       + (cc < 8 ? 0 : 64) + (cc & 7) * 8) * 2, src);
        }
        #pragma unroll
        for (int u = 0; u < 8; u++) {
            int idx = tid + u * 128;
            int r = idx >> 4, cc = idx & 15;
            const __nv_bfloat16* src = (cc < 8 ? HI : LO)
                + (mrow0 + jt * 64 + r) * QS + 2048 + hoff + (cc & 7) * 8;
            cp_async16(sVa + (uint32_t)(buf * VBUF + (cc < 8 ? r : 64 + r) * VSTR
                       + (cc & 7) * 8) * 2, src);
        }
        asm volatile("cp.async.commit_group;" ::: "memory");
    };

    issue_kv(0, 0);

    uint32_t qF[8][4];
    float oAcc[8][4] = {};
    float mS[2] = {-CUDART_INF_F, -CUDART_INF_F};
    float lS[2] = {0.0f, 0.0f};

    const int krow = (lane & 7) | ((lane >> 4) << 3);
    const int kc8  = ((lane >> 3) & 1) << 3;
    const int vrow = lane & 15;
    const int vc8  = (lane >> 4) << 3;
    const float sc = 0.18033688011112042f;              // 0.125 * log2(e)

    for (int jt = 0; jt <= qt; jt++) {
        const int buf = jt & 1;
        asm volatile("cp.async.wait_group 0;" ::: "memory");
        __syncthreads();
        if (jt == 0) {
            int rr = warp * 16 + (lane & 15);
            int cc = (lane >> 4) << 3;
            #pragma unroll
            for (int kg = 0; kg < 8; kg++)
                ldsm_x4(qF[kg], sQa + (uint32_t)((rr * QSTR + kg * 16 + cc) * 2));
        }
        if (jt < qt) issue_kv(jt + 1, buf ^ 1);

        const uint32_t kS = sKa + (uint32_t)(buf * KBUF) * 2;
        const uint32_t vS = sVa + (uint32_t)(buf * VBUF) * 2;

        float sAcc[8][4] = {};
        #pragma unroll
        for (int kg = 0; kg < 4; kg++) {
            uint32_t bF[4][4];
            #pragma unroll
            for (int np = 0; np < 4; np++)
                ldsm_x4(bF[np], kS + (uint32_t)(((np * 16 + krow) * QSTR + kg * 16 + kc8) * 2));
            #pragma unroll
            for (int np = 0; np < 4; np++) {
                MMA4(sAcc[2 * np],     qF[kg],     bF[np][0], bF[np][1]);
                MMA4(sAcc[2 * np + 1], qF[kg],     bF[np][2], bF[np][3]);
                MMA4(sAcc[2 * np],     qF[4 + kg], bF[np][0], bF[np][1]);
                MMA4(sAcc[2 * np + 1], qF[4 + kg], bF[np][2], bF[np][3]);
            }
        }
        #pragma unroll
        for (int kg = 0; kg < 4; kg++) {
            uint32_t bF[4][4];
            #pragma unroll
            for (int np = 0; np < 4; np++)
                ldsm_x4(bF[np], kS + (uint32_t)(((np * 16 + krow) * QSTR + 64 + kg * 16 + kc8) * 2));
            #pragma unroll
            for (int np = 0; np < 4; np++) {
                MMA4(sAcc[2 * np],     qF[kg], bF[np][0], bF[np][1]);
                MMA4(sAcc[2 * np + 1], qF[kg], bF[np][2], bF[np][3]);
            }
        }

        const bool diag = (jt == qt);
        #pragma unroll
        for (int nt = 0; nt < 8; nt++)
            #pragma unroll
            for (int e = 0; e < 4; e++) {
                float v = sAcc[nt][e] * sc;
                if (diag) {
                    int col = nt * 8 + 2 * t + (e & 1);
                    int row = warp * 16 + g + ((e >> 1) << 3);
                    if (col > row) v = -CUDART_INF_F;
                }
                sAcc[nt][e] = v;
            }
        #pragma unroll
        for (int hf = 0; hf < 2; hf++) {
            float mt = -CUDART_INF_F;
            #pragma unroll
            for (int nt = 0; nt < 8; nt++)
                mt = fmaxf(mt, fmaxf(sAcc[nt][2 * hf], sAcc[nt][2 * hf + 1]));
            mt = fmaxf(mt, __shfl_xor_sync(0xffffffffu, mt, 1));
            mt = fmaxf(mt, __shfl_xor_sync(0xffffffffu, mt, 2));
            float mn = fmaxf(mS[hf], mt);
            float alpha = ex2f(mS[hf] - mn);
            mS[hf] = mn;
            float ls = 0.0f;
            #pragma unroll
            for (int nt = 0; nt < 8; nt++) {
                float p0 = ex2f(sAcc[nt][2 * hf]     - mn);
                float p1 = ex2f(sAcc[nt][2 * hf + 1] - mn);
                sAcc[nt][2 * hf] = p0; sAcc[nt][2 * hf + 1] = p1;
                ls += p0 + p1;
            }
            ls += __shfl_xor_sync(0xffffffffu, ls, 1);
            ls += __shfl_xor_sync(0xffffffffu, ls, 2);
            lS[hf] = lS[hf] * alpha + ls;
            #pragma unroll
            for (int nt = 0; nt < 8; nt++) {
                oAcc[nt][2 * hf]     *= alpha;
                oAcc[nt][2 * hf + 1] *= alpha;
            }
        }

        #pragma unroll
        for (int kg = 0; kg < 4; kg++) {
            float p00 = sAcc[2*kg][0], p01 = sAcc[2*kg][1], p02 = sAcc[2*kg][2], p03 = sAcc[2*kg][3];
            float p10 = sAcc[2*kg+1][0], p11 = sAcc[2*kg+1][1], p12 = sAcc[2*kg+1][2], p13 = sAcc[2*kg+1][3];
            uint32_t aH[4] = { packbf(p00, p01), packbf(p02, p03),
                               packbf(p10, p11), packbf(p12, p13) };
            uint32_t aL[4] = { packbf(p00 - bfr(p00), p01 - bfr(p01)),
                               packbf(p02 - bfr(p02), p03 - bfr(p03)),
                               packbf(p10 - bfr(p10), p11 - bfr(p11)),
                               packbf(p12 - bfr(p12), p13 - bfr(p13)) };
            #pragma unroll
            for (int np = 0; np < 4; np++) {
                uint32_t bV[4];
                ldsm_x4_t(bV, vS + (uint32_t)(((kg * 16 + vrow) * VSTR + np * 16 + vc8) * 2));
                MMA4(oAcc[2 * np],     aH, bV[0], bV[1]);
                MMA4(oAcc[2 * np + 1], aH, bV[2], bV[3]);
                MMA4(oAcc[2 * np],     aL, bV[0], bV[1]);
                MMA4(oAcc[2 * np + 1], aL, bV[2], bV[3]);
            }
        }
        #pragma unroll
        for (int kg = 0; kg < 4; kg++) {
            float p00 = sAcc[2*kg][0], p01 = sAcc[2*kg][1], p02 = sAcc[2*kg][2], p03 = sAcc[2*kg][3];
            float p10 = sAcc[2*kg+1][0], p11 = sAcc[2*kg+1][1], p12 = sAcc[2*kg+1][2], p13 = sAcc[2*kg+1][3];
            uint32_t aH[4] = { packbf(p00, p01), packbf(p02, p03),
                               packbf(p10, p11), packbf(p12, p13) };
            #pragma unroll
            for (int np = 0; np < 4; np++) {
                uint32_t bV[4];
                ldsm_x4_t(bV, vS + (uint32_t)(((64 + kg * 16 + vrow) * VSTR + np * 16 + vc8) * 2));
                MMA4(oAcc[2 * np],     aH, bV[0], bV[1]);
                MMA4(oAcc[2 * np + 1], aH, bV[2], bV[3]);
            }
        }
    }

    // ---- epilogue: ctx hi/lo (deduplicated layout) ----
    float i0 = 1.0f / lS[0], i1 = 1.0f / lS[1];
    size_t r0 = mrow0 + qt * 64 + warp * 16 + g;
    #pragma unroll
    for (int nt = 0; nt < 8; nt++) {
        int col = hoff + nt * 8 + 2 * t;
        float v0 = oAcc[nt][0] * i0, v1 = oAcc[nt][1] * i0;
        float v2 = oAcc[nt][2] * i1, v3 = oAcc[nt][3] * i1;
        *(uint32_t*)&CChi[r0 * D_MODEL + col]       = packbf(v0, v1);
        *(uint32_t*)&CClo[r0 * D_MODEL + col]       = packbf(v0 - bfr(v0), v1 - bfr(v1));
        *(uint32_t*)&CChi[(r0 + 8) * D_MODEL + col] = packbf(v2, v3);
        *(uint32_t*)&CClo[(r0 + 8) * D_MODEL + col] = packbf(v2 - bfr(v2), v3 - bfr(v3));
    }
}

// ---------------- launcher ----------------
extern "C" void kernel_launch(void* const* d_in, const int* in_sizes, int n_in,
                              void* d_out, int out_size)
{
    const float* x  = (const float*)d_in[0];
    const float* Wq = (const float*)d_in[1];
    const float* Wk = (const float*)d_in[2];
    const float* Wv = (const float*)d_in[3];
    const float* Wo = (const float*)d_in[4];
    const float* bo = (const float*)d_in[5];
    float* out = (float*)d_out;

    __nv_bfloat16 *xhi, *xlo, *whi, *wlo, *wohi, *wolo, *hi, *lo, *chi, *clo;
    cudaGetSymbolAddress((void**)&xhi, g_xhi);
    cudaGetSymbolAddress((void**)&xlo, g_xlo);
    cudaGetSymbolAddress((void**)&whi, g_whi);
    cudaGetSymbolAddress((void**)&wlo, g_wlo);
    cudaGetSymbolAddress((void**)&wohi, g_wohi);
    cudaGetSymbolAddress((void**)&wolo, g_wolo);
    cudaGetSymbolAddress((void**)&hi, g_hi);
    cudaGetSymbolAddress((void**)&lo, g_lo);
    cudaGetSymbolAddress((void**)&chi, g_chi);
    cudaGetSymbolAddress((void**)&clo, g_clo);

    static bool attr_done = false;
    if (!attr_done) {
        cudaFuncSetAttribute(mgemm_kernel,
                             cudaFuncAttributeMaxDynamicSharedMemorySize, G_SMEM);
        cudaFuncSetAttribute(attn_tc_kernel,
                             cudaFuncAttributeMaxDynamicSharedMemorySize, ATT_SMEM);
        attr_done = true;
    }

    convert_a_kernel<<<(MTOT * KD) / 256, 256>>>(x, xhi, xlo, MTOT);
    dim3 gridW(32, 32), blockW(32, 8);
    convert_w_kernel<<<gridW, blockW>>>(Wq, whi, wlo);
    convert_w_kernel<<<gridW, blockW>>>(Wk, whi + (size_t)1024 * KD, wlo + (size_t)1024 * KD);
    convert_w_kernel<<<gridW, blockW>>>(Wv, whi + (size_t)2048 * KD, wlo + (size_t)2048 * KD);
    convert_w_kernel<<<gridW, blockW>>>(Wo, wohi, wolo);

    // fused QKV GEMM: N = 3072, bf16 hi/lo epilogue
    dim3 gridQKV(QS / GBN, MTOT / GBM);      // (24, 64)
    mgemm_kernel<<<gridQKV, 256, G_SMEM>>>(xhi, xlo, whi, wlo, nullptr,
                                           nullptr, hi, lo, QS, 1);

    dim3 gridA(SEQ / 64, NHEAD, BATCH);      // (32, 16, 4)
    attn_tc_kernel<<<gridA, 128, ATT_SMEM>>>(hi, lo, chi, clo);

    // output GEMM: fp32 + bias
    dim3 gridO(D_MODEL / GBN, MTOT / GBM);   // (8, 64)
    mgemm_kernel<<<gridO, 256, G_SMEM>>>(chi, clo, wohi, wolo, bo,
                                         out, nullptr, nullptr, D_MODEL, 0);
}

// round 8
// speedup vs baseline: 7.2950x; 2.6390x over previous
#include <cuda_runtime.h>
#include <cuda_fp16.h>
#include <math_constants.h>
#include <cstdint>

#define D_MODEL 1024
#define SEQ     2048
#define BATCH   4
#define NHEAD   16
#define HDIM    64
#define MTOT    (BATCH * SEQ)
#define KD      1024
#define QS      3072               // fused qkv row stride

// -------- scratch (allocation-free: __device__ globals) --------
__device__ __align__(16) __half g_xh[(size_t)MTOT * KD];
__device__ __align__(16) __half g_wh[(size_t)QS * KD];      // [Wq|Wk|Wv] transposed
__device__ __align__(16) __half g_woh[(size_t)D_MODEL * KD];
__device__ __align__(16) __half g_qkv[(size_t)MTOT * QS];
__device__ __align__(16) __half g_ch[(size_t)MTOT * D_MODEL];

// ---------------- small helpers ----------------
__device__ __forceinline__ uint32_t packh(float lo, float hi) {
    uint32_t d;
    asm("cvt.rn.f16x2.f32 %0, %1, %2;" : "=r"(d) : "f"(hi), "f"(lo));
    return d;
}
__device__ __forceinline__ float ex2f(float x) {
    float y; asm("ex2.approx.ftz.f32 %0, %1;" : "=f"(y) : "f"(x)); return y;
}
__device__ __forceinline__ void ldsm_x4(uint32_t* r, uint32_t a) {
    asm volatile("ldmatrix.sync.aligned.m8n8.x4.shared.b16 {%0,%1,%2,%3}, [%4];"
        : "=r"(r[0]), "=r"(r[1]), "=r"(r[2]), "=r"(r[3]) : "r"(a));
}
__device__ __forceinline__ void ldsm_x4_t(uint32_t* r, uint32_t a) {
    asm volatile("ldmatrix.sync.aligned.m8n8.x4.trans.shared.b16 {%0,%1,%2,%3}, [%4];"
        : "=r"(r[0]), "=r"(r[1]), "=r"(r[2]), "=r"(r[3]) : "r"(a));
}
__device__ __forceinline__ void cp_async16(uint32_t smem, const void* gptr) {
    asm volatile("cp.async.cg.shared.global [%0], [%1], 16;\n"
                 :: "r"(smem), "l"(gptr) : "memory");
}
__device__ __forceinline__ uint32_t smem_u32(const void* p) {
    return (uint32_t)__cvta_generic_to_shared(p);
}

#define MMA4H(d, a, b0, b1)                                                   \
    asm volatile(                                                             \
        "mma.sync.aligned.m16n8k16.row.col.f32.f16.f16.f32 "                  \
        "{%0,%1,%2,%3}, {%4,%5,%6,%7}, {%8,%9}, {%0,%1,%2,%3};"               \
        : "+f"(d[0]), "+f"(d[1]), "+f"(d[2]), "+f"(d[3])                      \
        : "r"(a[0]), "r"(a[1]), "r"(a[2]), "r"(a[3]), "r"(b0), "r"(b1))

// ---------------- conversion kernels ----------------
__global__ void convert_a_kernel(const float* __restrict__ X,
                                 __half* __restrict__ O, int n)
{
    int i = blockIdx.x * blockDim.x + threadIdx.x;
    float4 f = *(const float4*)(X + (size_t)i * 4);
    uint2 p = make_uint2(packh(f.x, f.y), packh(f.z, f.w));
    *(uint2*)(O + (size_t)i * 4) = p;
}

// Weight transpose via smem tile; O pre-offset to the destination row block.
__global__ void convert_w_kernel(const float* __restrict__ W,
                                 __half* __restrict__ O)
{
    __shared__ float tile[32][33];
    const int n0 = blockIdx.x * 32, k0 = blockIdx.y * 32;
    const int tx = threadIdx.x, ty = threadIdx.y;      // (32, 8)
    #pragma unroll
    for (int i = 0; i < 4; i++)
        tile[ty + 8 * i][tx] = W[(size_t)(k0 + ty + 8 * i) * D_MODEL + n0 + tx];
    __syncthreads();
    #pragma unroll
    for (int i = 0; i < 4; i++) {
        int r = ty + 8 * i;
        O[(size_t)(n0 + r) * KD + k0 + tx] = __float2half(tile[tx][r]);
    }
}

// ---------------- fp16 mma.sync GEMM, ldmatrix mainloop, 3-stage cp.async --------
// C[M,N] = A[M,K] @ Bt[N,K]^T.  mode 0: fp32 C + bias.  mode 1: fp16 C.
#define GBM 128
#define GBN 128
#define SSTR 72
#define MST  3
#define TILE_E (GBM * SSTR)
#define G_SMEM (2 * MST * TILE_E * 2)           // 110592 bytes
#define G_NIT  (KD / 64)                        // 16 chunks

__global__ __launch_bounds__(256, 2) void mgemm_kernel(
    const __half* __restrict__ A,
    const __half* __restrict__ Bt,
    const float* __restrict__ bias,
    float* __restrict__ Cf,
    __half* __restrict__ Ch,
    int N, int mode)
{
    extern __shared__ __half sm[];
    __half* sA = sm;
    __half* sB = sm + MST * TILE_E;

    const int tid  = threadIdx.x;
    const int warp = tid >> 5, lane = tid & 31;
    const int bm = blockIdx.y * GBM;
    const int bn = blockIdx.x * GBN;
    const int wm = warp >> 1, wn = warp & 1;
    const int m_base = wm * 32, n_base = wn * 64;
    const int g = lane >> 2, t = lane & 3;
    const int lrow = lane & 15, lcolb = ((lane >> 4) << 3) * 2;

    const uint32_t sA0 = smem_u32(sA);
    const uint32_t sB0 = smem_u32(sB);

    float acc[2][8][4] = {};

    auto issue = [&](int it) {
        const int s = it % MST;
        const int k0 = it * 64;
        #pragma unroll
        for (int i = 0; i < 4; i++) {
            int idx = tid + i * 256;
            int row = idx >> 3, c16 = idx & 7;
            uint32_t o = (uint32_t)((s * GBM + row) * SSTR + c16 * 8) * 2;
            cp_async16(sA0 + o, A + (size_t)(bm + row) * KD + k0 + c16 * 8);
            cp_async16(sB0 + o, Bt + (size_t)(bn + row) * KD + k0 + c16 * 8);
        }
        asm volatile("cp.async.commit_group;" ::: "memory");
    };

    issue(0); issue(1);

    for (int it = 0; it < G_NIT; ++it) {
        if (it == G_NIT - 1) asm volatile("cp.async.wait_group 0;" ::: "memory");
        else                 asm volatile("cp.async.wait_group 1;" ::: "memory");
        __syncthreads();
        if (it + 2 < G_NIT) issue(it + 2);

        const uint32_t aS = sA0 + (uint32_t)((it % MST) * TILE_E) * 2;
        const uint32_t bS = sB0 + (uint32_t)((it % MST) * TILE_E) * 2;

        #pragma unroll
        for (int ks = 0; ks < 4; ks++) {
            const uint32_t kb = (uint32_t)(ks * 32) + lcolb;
            uint32_t aF[2][4], bF[4][4];
            #pragma unroll
            for (int mt = 0; mt < 2; mt++)
                ldsm_x4(aF[mt], aS + (uint32_t)((m_base + mt * 16 + lrow) * SSTR) * 2 + kb);
            #pragma unroll
            for (int nt = 0; nt < 4; nt++)
                ldsm_x4(bF[nt], bS + (uint32_t)((n_base + nt * 16 + lrow) * SSTR) * 2 + kb);
            #pragma unroll
            for (int mt = 0; mt < 2; mt++)
                #pragma unroll
                for (int nt = 0; nt < 4; nt++) {
                    MMA4H(acc[mt][2 * nt],     aF[mt], bF[nt][0], bF[nt][2]);
                    MMA4H(acc[mt][2 * nt + 1], aF[mt], bF[nt][1], bF[nt][3]);
                }
        }
    }

    if (mode == 0) {
        #pragma unroll
        for (int mt = 0; mt < 2; mt++) {
            int r0 = bm + m_base + mt * 16 + g;
            #pragma unroll
            for (int nt = 0; nt < 8; nt++) {
                int col = bn + n_base + nt * 8 + 2 * t;
                float b0 = bias[col], b1 = bias[col + 1];
                *(float2*)&Cf[(size_t)r0 * N + col] =
                    make_float2(acc[mt][nt][0] + b0, acc[mt][nt][1] + b1);
                *(float2*)&Cf[(size_t)(r0 + 8) * N + col] =
                    make_float2(acc[mt][nt][2] + b0, acc[mt][nt][3] + b1);
            }
        }
    } else {
        #pragma unroll
        for (int mt = 0; mt < 2; mt++) {
            int r0 = bm + m_base + mt * 16 + g;
            #pragma unroll
            for (int nt = 0; nt < 8; nt++) {
                int col = bn + n_base + nt * 8 + 2 * t;
                *(uint32_t*)&Ch[(size_t)r0 * N + col] =
                    packh(acc[mt][nt][0], acc[mt][nt][1]);
                *(uint32_t*)&Ch[(size_t)(r0 + 8) * N + col] =
                    packh(acc[mt][nt][2], acc[mt][nt][3]);
            }
        }
    }
}

// ---------------- flash attention: single fp16, double-buffered K/V ----------------
#define QSTR 72
#define TBUF (64 * QSTR)
#define ATT_SMEM (5 * TBUF * 2)                 // 46080 bytes

__global__ __launch_bounds__(128) void attn_tc_kernel(
    const __half* __restrict__ QKV,
    __half* __restrict__ CC)
{
    extern __shared__ __half sm_at[];
    __half* sQ = sm_at;
    __half* sK = sQ + TBUF;
    __half* sV = sK + 2 * TBUF;

    const int tid  = threadIdx.x;
    const int warp = tid >> 5, lane = tid & 31;
    const int g = lane >> 2, t = lane & 3;
    const int qt = blockIdx.x, h = blockIdx.y, b = blockIdx.z;
    const int hoff = h * HDIM;
    const size_t mrow0 = (size_t)b * SEQ;

    const uint32_t sQa = smem_u32(sQ);
    const uint32_t sKa = smem_u32(sK);
    const uint32_t sVa = smem_u32(sV);

    // ---- Q tile: 64 rows x 64 cols fp16 = 512 x 16B chunks, 128 threads x 4 ----
    #pragma unroll
    for (int u = 0; u < 4; u++) {
        int idx = tid + u * 128;
        int r = idx >> 3, c16 = idx & 7;
        cp_async16(sQa + (uint32_t)(r * QSTR + c16 * 8) * 2,
                   QKV + (mrow0 + qt * 64 + r) * QS + hoff + c16 * 8);
    }

    auto issue_kv = [&](int jt, int buf) {
        #pragma unroll
        for (int u = 0; u < 4; u++) {
            int idx = tid + u * 128;
            int r = idx >> 3, c16 = idx & 7;
            cp_async16(sKa + (uint32_t)(buf * TBUF + r * QSTR + c16 * 8) * 2,
                       QKV + (mrow0 + jt * 64 + r) * QS + 1024 + hoff + c16 * 8);
        }
        #pragma unroll
        for (int u = 0; u < 4; u++) {
            int idx = tid + u * 128;
            int r = idx >> 3, c16 = idx & 7;
            cp_async16(sVa + (uint32_t)(buf * TBUF + r * QSTR + c16 * 8) * 2,
                       QKV + (mrow0 + jt * 64 + r) * QS + 2048 + hoff + c16 * 8);
        }
        asm volatile("cp.async.commit_group;" ::: "memory");
    };

    issue_kv(0, 0);

    uint32_t qF[4][4];
    float oAcc[8][4] = {};
    float mS[2] = {-CUDART_INF_F, -CUDART_INF_F};
    float lS[2] = {0.0f, 0.0f};

    const int krow = (lane & 7) | ((lane >> 4) << 3);
    const int kc8  = ((lane >> 3) & 1) << 3;
    const int vrow = lane & 15;
    const int vc8  = (lane >> 4) << 3;
    const float sc = 0.18033688011112042f;              // 0.125 * log2(e)

    for (int jt = 0; jt <= qt; jt++) {
        const int buf = jt & 1;
        asm volatile("cp.async.wait_group 0;" ::: "memory");
        __syncthreads();
        if (jt == 0) {
            int rr = warp * 16 + (lane & 15);
            int cc = (lane >> 4) << 3;
            #pragma unroll
            for (int kg = 0; kg < 4; kg++)
                ldsm_x4(qF[kg], sQa + (uint32_t)((rr * QSTR + kg * 16 + cc) * 2));
        }
        if (jt < qt) issue_kv(jt + 1, buf ^ 1);

        const uint32_t kS = sKa + (uint32_t)(buf * TBUF) * 2;
        const uint32_t vS = sVa + (uint32_t)(buf * TBUF) * 2;

        // ---- S = Q K^T ----
        float sAcc[8][4] = {};
        #pragma unroll
        for (int kg = 0; kg < 4; kg++) {
            uint32_t bF[4][4];
            #pragma unroll
            for (int np = 0; np < 4; np++)
                ldsm_x4(bF[np], kS + (uint32_t)(((np * 16 + krow) * QSTR + kg * 16 + kc8) * 2));
            #pragma unroll
            for (int np = 0; np < 4; np++) {
                MMA4H(sAcc[2 * np],     qF[kg], bF[np][0], bF[np][1]);
                MMA4H(sAcc[2 * np + 1], qF[kg], bF[np][2], bF[np][3]);
            }
        }

        // ---- online softmax (log2 domain) ----
        const bool diag = (jt == qt);
        #pragma unroll
        for (int nt = 0; nt < 8; nt++)
            #pragma unroll
            for (int e = 0; e < 4; e++) {
                float v = sAcc[nt][e] * sc;
                if (diag) {
                    int col = nt * 8 + 2 * t + (e & 1);
                    int row = warp * 16 + g + ((e >> 1) << 3);
                    if (col > row) v = -CUDART_INF_F;
                }
                sAcc[nt][e] = v;
            }
        #pragma unroll
        for (int hf = 0; hf < 2; hf++) {
            float mt = -CUDART_INF_F;
            #pragma unroll
            for (int nt = 0; nt < 8; nt++)
                mt = fmaxf(mt, fmaxf(sAcc[nt][2 * hf], sAcc[nt][2 * hf + 1]));
            mt = fmaxf(mt, __shfl_xor_sync(0xffffffffu, mt, 1));
            mt = fmaxf(mt, __shfl_xor_sync(0xffffffffu, mt, 2));
            float mn = fmaxf(mS[hf], mt);
            float alpha = ex2f(mS[hf] - mn);
            mS[hf] = mn;
            float ls = 0.0f;
            #pragma unroll
            for (int nt = 0; nt < 8; nt++) {
                float p0 = ex2f(sAcc[nt][2 * hf]     - mn);
                float p1 = ex2f(sAcc[nt][2 * hf + 1] - mn);
                sAcc[nt][2 * hf] = p0; sAcc[nt][2 * hf + 1] = p1;
                ls += p0 + p1;
            }
            ls += __shfl_xor_sync(0xffffffffu, ls, 1);
            ls += __shfl_xor_sync(0xffffffffu, ls, 2);
            lS[hf] = lS[hf] * alpha + ls;
            #pragma unroll
            for (int nt = 0; nt < 8; nt++) {
                oAcc[nt][2 * hf]     *= alpha;
                oAcc[nt][2 * hf + 1] *= alpha;
            }
        }

        // ---- O += P V ----
        #pragma unroll
        for (int kg = 0; kg < 4; kg++) {
            uint32_t aH[4] = {
                packh(sAcc[2*kg][0],   sAcc[2*kg][1]),
                packh(sAcc[2*kg][2],   sAcc[2*kg][3]),
                packh(sAcc[2*kg+1][0], sAcc[2*kg+1][1]),
                packh(sAcc[2*kg+1][2], sAcc[2*kg+1][3]) };
            #pragma unroll
            for (int np = 0; np < 4; np++) {
                uint32_t bV[4];
                ldsm_x4_t(bV, vS + (uint32_t)(((kg * 16 + vrow) * QSTR + np * 16 + vc8) * 2));
                MMA4H(oAcc[2 * np],     aH, bV[0], bV[1]);
                MMA4H(oAcc[2 * np + 1], aH, bV[2], bV[3]);
            }
        }
    }

    // ---- epilogue: ctx fp16 ----
    float i0 = 1.0f / lS[0], i1 = 1.0f / lS[1];
    size_t r0 = mrow0 + qt * 64 + warp * 16 + g;
    #pragma unroll
    for (int nt = 0; nt < 8; nt++) {
        int col = hoff + nt * 8 + 2 * t;
        *(uint32_t*)&CC[r0 * D_MODEL + col] =
            packh(oAcc[nt][0] * i0, oAcc[nt][1] * i0);
        *(uint32_t*)&CC[(r0 + 8) * D_MODEL + col] =
            packh(oAcc[nt][2] * i1, oAcc[nt][3] * i1);
    }
}

// ---------------- launcher ----------------
extern "C" void kernel_launch(void* const* d_in, const int* in_sizes, int n_in,
                              void* d_out, int out_size)
{
    const float* x  = (const float*)d_in[0];
    const float* Wq = (const float*)d_in[1];
    const float* Wk = (const float*)d_in[2];
    const float* Wv = (const float*)d_in[3];
    const float* Wo = (const float*)d_in[4];
    const float* bo = (const float*)d_in[5];
    float* out = (float*)d_out;

    __half *xh, *wh, *woh, *qkv, *ch;
    cudaGetSymbolAddress((void**)&xh, g_xh);
    cudaGetSymbolAddress((void**)&wh, g_wh);
    cudaGetSymbolAddress((void**)&woh, g_woh);
    cudaGetSymbolAddress((void**)&qkv, g_qkv);
    cudaGetSymbolAddress((void**)&ch, g_ch);

    static bool attr_done = false;
    if (!attr_done) {
        cudaFuncSetAttribute(mgemm_kernel,
                             cudaFuncAttributeMaxDynamicSharedMemorySize, G_SMEM);
        cudaFuncSetAttribute(attn_tc_kernel,
                             cudaFuncAttributeMaxDynamicSharedMemorySize, ATT_SMEM);
        attr_done = true;
    }

    convert_a_kernel<<<(MTOT * KD / 4) / 256, 256>>>(x, xh, MTOT * KD / 4);
    dim3 gridW(32, 32), blockW(32, 8);
    convert_w_kernel<<<gridW, blockW>>>(Wq, wh);
    convert_w_kernel<<<gridW, blockW>>>(Wk, wh + (size_t)1024 * KD);
    convert_w_kernel<<<gridW, blockW>>>(Wv, wh + (size_t)2048 * KD);
    convert_w_kernel<<<gridW, blockW>>>(Wo, woh);

    // fused QKV GEMM: N = 3072, fp16 epilogue
    dim3 gridQKV(QS / GBN, MTOT / GBM);      // (24, 64)
    mgemm_kernel<<<gridQKV, 256, G_SMEM>>>(xh, wh, nullptr,
                                           nullptr, qkv, QS, 1);

    dim3 gridA(SEQ / 64, NHEAD, BATCH);      // (32, 16, 4)
    attn_tc_kernel<<<gridA, 128, ATT_SMEM>>>(qkv, ch);

    // output GEMM: fp32 + bias
    dim3 gridO(D_MODEL / GBN, MTOT / GBM);   // (8, 64)
    mgemm_kernel<<<gridO, 256, G_SMEM>>>(ch, woh, bo,
                                         out, nullptr, D_MODEL, 0);
}